// round 1
// baseline (speedup 1.0000x reference)
#include <cuda_runtime.h>

// ---------------------------------------------------------------------------
// Submanifold sparse conv2d, B=4, H=W=1024, C=K=64, 3x3, stride1/pad1/dil1.
// out[n,k] = bias[k] + sum_{active taps t} features[nbr_t(n),:] . weight[k,t,:]
//
// Pipeline:
//   wprep   : weight [K][3][3][C] -> d_wT [tap][c][k]   (coalesced SMEM loads later)
//   scatter : d_grid[flat] = n+1  (0 = empty; static zero-init), zero counters
//   build   : per-point neighbor probes -> 8 compacted per-tap (out,in) pair lists
//   center  : dense N x 64 x 64 GEMM + bias (tap 4, nbr == self), direct store
//   tap     : per-tap pair-list GEMM, atomicAdd accumulate into out
// ---------------------------------------------------------------------------

#define HH 1024
#define WW 1024
#define NMAX 400000

__device__ int    d_grid[1 << 22];        // 16 MB, zero-init; stores row+1, 0 = empty
__device__ int2   d_pairs[8][NMAX];       // per off-center tap: (out_row, in_row)
__device__ int    d_cnt[8];
__device__ float  d_wT[9 * 64 * 64];      // [tap][c][k]

// ---------------- weight transpose: [k][tap][c] -> [tap][c][k] ----------------
__global__ void wprep_kernel(const float* __restrict__ wgt) {
    int idx = blockIdx.x * 256 + threadIdx.x;
    if (idx < 9 * 64 * 64) {
        int k = idx & 63, c = (idx >> 6) & 63, tap = idx >> 12;
        d_wT[idx] = wgt[((k * 9 + tap) << 6) + c];
    }
}

// ---------------- scatter rows into dense hash grid ----------------
__global__ void scatter_kernel(const int* __restrict__ idxs, int n) {
    int gid = blockIdx.x * 256 + threadIdx.x;
    if (gid < 8) d_cnt[gid] = 0;
    if (gid < n) {
        int b = idxs[gid * 3], h = idxs[gid * 3 + 1], w = idxs[gid * 3 + 2];
        d_grid[(b << 20) + (h << 10) + w] = gid + 1;
    }
}

// ---------------- build compacted per-tap pair lists ----------------
__global__ void build_kernel(const int* __restrict__ idxs, int n) {
    int gid  = blockIdx.x * 256 + threadIdx.x;
    int warp = threadIdx.x >> 5, lane = threadIdx.x & 31;
    __shared__ int warpoff[8][8];   // [tap][warp] -> exclusive offsets
    __shared__ int blockbase[8];

    bool valid = gid < n;
    int b = 0, h = 0, w = 0;
    if (valid) { b = idxs[gid * 3]; h = idxs[gid * 3 + 1]; w = idxs[gid * 3 + 2]; }

    int nbr[8];
    bool act[8];
    unsigned masks[8];
#pragma unroll
    for (int tt = 0; tt < 8; tt++) {
        int wt = tt + (tt >= 4 ? 1 : 0);       // skip center (tap 4)
        int r = wt / 3, s = wt - r * 3;
        int hi = h + r - 1, wi = w + s - 1;
        bool ib = valid && ((unsigned)hi < HH) && ((unsigned)wi < WW);
        int g = 0;
        if (ib) g = d_grid[(b << 20) + (hi << 10) + wi];
        nbr[tt] = g - 1;
        act[tt] = g > 0;
        masks[tt] = __ballot_sync(0xffffffffu, act[tt]);
    }
    if (lane == 0) {
#pragma unroll
        for (int tt = 0; tt < 8; tt++) warpoff[tt][warp] = __popc(masks[tt]);
    }
    __syncthreads();
    if (threadIdx.x < 8) {
        int tt = threadIdx.x, tot = 0;
#pragma unroll
        for (int w2 = 0; w2 < 8; w2++) { int v = warpoff[tt][w2]; warpoff[tt][w2] = tot; tot += v; }
        blockbase[tt] = tot ? atomicAdd(&d_cnt[tt], tot) : 0;
    }
    __syncthreads();
#pragma unroll
    for (int tt = 0; tt < 8; tt++) {
        if (act[tt]) {
            int rank = __popc(masks[tt] & ((1u << lane) - 1u));
            int pos  = blockbase[tt] + warpoff[tt][warp] + rank;
            d_pairs[tt][pos] = make_int2(gid, nbr[tt]);
        }
    }
}

// ---------------- center tap: dense GEMM + bias, direct store ----------------
// Block = 128 threads, 32 points. Warp wq handles k in [16*wq, 16*wq+16),
// lane owns point p. Weights broadcast via LDS.128; features from padded
// [c][p] stage (bank (c+p)%32, conflict-free).
__global__ __launch_bounds__(128) void center_kernel(
        const float* __restrict__ feat, const float* __restrict__ bias,
        float* __restrict__ out, int n) {
    __shared__ float wsm[4096];
    __shared__ float fs[64 * 33];
    int t = threadIdx.x;

    const float4* wsrc = (const float4*)(d_wT + 4 * 4096);
#pragma unroll
    for (int i = 0; i < 8; i++) ((float4*)wsm)[t + i * 128] = wsrc[t + i * 128];

    int base = blockIdx.x * 32;
    int p = t >> 2, q = t & 3, c0 = q * 16;
    int row = base + p;
    if (row < n) {
        const float4* fr = (const float4*)(feat + row * 64 + c0);
#pragma unroll
        for (int i = 0; i < 4; i++) {
            float4 v = fr[i];
            fs[(c0 + i * 4 + 0) * 33 + p] = v.x;
            fs[(c0 + i * 4 + 1) * 33 + p] = v.y;
            fs[(c0 + i * 4 + 2) * 33 + p] = v.z;
            fs[(c0 + i * 4 + 3) * 33 + p] = v.w;
        }
    }
    __syncthreads();

    int wq = t >> 5, lane = t & 31;
    float acc[16];
#pragma unroll
    for (int j = 0; j < 16; j++) acc[j] = 0.f;
    const float* wbase = wsm + wq * 16;
#pragma unroll 8
    for (int c = 0; c < 64; c++) {
        float f = fs[c * 33 + lane];
        const float4* wr = (const float4*)(wbase + c * 64);
        float4 w0 = wr[0], w1 = wr[1], w2 = wr[2], w3 = wr[3];
        acc[0]  += f * w0.x; acc[1]  += f * w0.y; acc[2]  += f * w0.z; acc[3]  += f * w0.w;
        acc[4]  += f * w1.x; acc[5]  += f * w1.y; acc[6]  += f * w1.z; acc[7]  += f * w1.w;
        acc[8]  += f * w2.x; acc[9]  += f * w2.y; acc[10] += f * w2.z; acc[11] += f * w2.w;
        acc[12] += f * w3.x; acc[13] += f * w3.y; acc[14] += f * w3.z; acc[15] += f * w3.w;
    }

    int orow = base + lane;
    if (orow < n) {
        float* o = out + orow * 64 + wq * 16;
        const float4* bb = (const float4*)(bias + wq * 16);
#pragma unroll
        for (int i = 0; i < 4; i++) {
            float4 bv = bb[i];
            ((float4*)o)[i] = make_float4(acc[i * 4 + 0] + bv.x, acc[i * 4 + 1] + bv.y,
                                          acc[i * 4 + 2] + bv.z, acc[i * 4 + 3] + bv.w);
        }
    }
}

// ---------------- off-center taps: pair-list GEMM, atomic accumulate ----------------
__global__ __launch_bounds__(128) void tap_kernel(
        const float* __restrict__ feat, float* __restrict__ out) {
    int tap  = blockIdx.y;
    int cnt  = d_cnt[tap];
    int base = blockIdx.x * 32;
    if (base >= cnt) return;

    __shared__ float wsm[4096];
    __shared__ float fs[64 * 33];
    __shared__ int2  prs[32];
    int t = threadIdx.x;

    if (t < 32) {
        int idx = base + t;
        prs[t] = (idx < cnt) ? d_pairs[tap][idx] : make_int2(-1, -1);
    }
    int wtap = tap + (tap >= 4 ? 1 : 0);
    const float4* wsrc = (const float4*)(d_wT + wtap * 4096);
#pragma unroll
    for (int i = 0; i < 8; i++) ((float4*)wsm)[t + i * 128] = wsrc[t + i * 128];
    __syncthreads();

    int p = t >> 2, q = t & 3, c0 = q * 16;
    int in = prs[p].y;
    if (in >= 0) {
        const float4* fr = (const float4*)(feat + in * 64 + c0);
#pragma unroll
        for (int i = 0; i < 4; i++) {
            float4 v = fr[i];
            fs[(c0 + i * 4 + 0) * 33 + p] = v.x;
            fs[(c0 + i * 4 + 1) * 33 + p] = v.y;
            fs[(c0 + i * 4 + 2) * 33 + p] = v.z;
            fs[(c0 + i * 4 + 3) * 33 + p] = v.w;
        }
    }
    __syncthreads();

    int wq = t >> 5, lane = t & 31;
    float acc[16];
#pragma unroll
    for (int j = 0; j < 16; j++) acc[j] = 0.f;
    const float* wbase = wsm + wq * 16;
#pragma unroll 8
    for (int c = 0; c < 64; c++) {
        float f = fs[c * 33 + lane];
        const float4* wr = (const float4*)(wbase + c * 64);
        float4 w0 = wr[0], w1 = wr[1], w2 = wr[2], w3 = wr[3];
        acc[0]  += f * w0.x; acc[1]  += f * w0.y; acc[2]  += f * w0.z; acc[3]  += f * w0.w;
        acc[4]  += f * w1.x; acc[5]  += f * w1.y; acc[6]  += f * w1.z; acc[7]  += f * w1.w;
        acc[8]  += f * w2.x; acc[9]  += f * w2.y; acc[10] += f * w2.z; acc[11] += f * w2.w;
        acc[12] += f * w3.x; acc[13] += f * w3.y; acc[14] += f * w3.z; acc[15] += f * w3.w;
    }

    int orow = prs[lane].x;
    if (orow >= 0) {
        float* o = out + orow * 64 + wq * 16;
#pragma unroll
        for (int j = 0; j < 16; j++) atomicAdd(o + j, acc[j]);
    }
}

// ---------------- launch ----------------
extern "C" void kernel_launch(void* const* d_in, const int* in_sizes, int n_in,
                              void* d_out, int out_size) {
    const float* feat = (const float*)d_in[0];
    const int*   idxs = (const int*)d_in[1];
    const float* wgt  = (const float*)d_in[2];
    const float* bias = (const float*)d_in[3];
    float* out = (float*)d_out;
    int n = in_sizes[0] / 64;

    wprep_kernel<<<144, 256>>>(wgt);
    scatter_kernel<<<(n + 255) / 256, 256>>>(idxs, n);
    build_kernel<<<(n + 255) / 256, 256>>>(idxs, n);
    center_kernel<<<(n + 31) / 32, 128>>>(feat, bias, out, n);
    dim3 g4((n + 31) / 32, 8, 1);
    tap_kernel<<<g4, 128>>>(feat, out);
}

// round 2
// speedup vs baseline: 1.7515x; 1.7515x over previous
#include <cuda_runtime.h>

// ---------------------------------------------------------------------------
// Submanifold sparse conv2d, B=4, H=W=1024, C=K=64, 3x3, stride1/pad1/dil1.
//
// Pipeline:
//   wprep   : weight [K][3][3][C] -> d_wT [tap][c][k]
//   scatter : d_grid[flat] = n+1  (0 = empty; static zero-init), zero counters
//   build   : per-point neighbor probes -> 8 compacted per-tap (out,in) lists
//   center  : dense 128x64 register-blocked GEMM + bias, direct store
//   tap     : pair-list 128x64 register-blocked GEMM, red.v4 accumulate
// ---------------------------------------------------------------------------

#define HH 1024
#define WW 1024
#define NMAX 400000

__device__ int    d_grid[1 << 22];        // stores row+1, 0 = empty (zero-init)
__device__ int2   d_pairs[8][NMAX];       // per off-center tap: (out_row, in_row)
__device__ int    d_cnt[8];
__device__ float  d_wT[9 * 64 * 64];      // [tap][c][k]

// ---------------- weight transpose: [k][tap][c] -> [tap][c][k] ----------------
__global__ void wprep_kernel(const float* __restrict__ wgt) {
    int idx = blockIdx.x * 256 + threadIdx.x;
    if (idx < 9 * 64 * 64) {
        int k = idx & 63, c = (idx >> 6) & 63, tap = idx >> 12;
        d_wT[idx] = wgt[((k * 9 + tap) << 6) + c];
    }
}

// ---------------- scatter rows into dense hash grid ----------------
__global__ void scatter_kernel(const int* __restrict__ idxs, int n) {
    int gid = blockIdx.x * 256 + threadIdx.x;
    if (gid < 8) d_cnt[gid] = 0;
    if (gid < n) {
        int b = idxs[gid * 3], h = idxs[gid * 3 + 1], w = idxs[gid * 3 + 2];
        d_grid[(b << 20) + (h << 10) + w] = gid + 1;
    }
}

// ---------------- build compacted per-tap pair lists ----------------
__global__ void build_kernel(const int* __restrict__ idxs, int n) {
    int gid  = blockIdx.x * 256 + threadIdx.x;
    int warp = threadIdx.x >> 5, lane = threadIdx.x & 31;
    __shared__ int warpoff[8][8];
    __shared__ int blockbase[8];

    bool valid = gid < n;
    int b = 0, h = 0, w = 0;
    if (valid) { b = idxs[gid * 3]; h = idxs[gid * 3 + 1]; w = idxs[gid * 3 + 2]; }

    int nbr[8];
    bool act[8];
    unsigned masks[8];
#pragma unroll
    for (int tt = 0; tt < 8; tt++) {
        int wt = tt + (tt >= 4 ? 1 : 0);       // skip center (tap 4)
        int r = wt / 3, s = wt - r * 3;
        int hi = h + r - 1, wi = w + s - 1;
        bool ib = valid && ((unsigned)hi < HH) && ((unsigned)wi < WW);
        int g = 0;
        if (ib) g = d_grid[(b << 20) + (hi << 10) + wi];
        nbr[tt] = g - 1;
        act[tt] = g > 0;
        masks[tt] = __ballot_sync(0xffffffffu, act[tt]);
    }
    if (lane == 0) {
#pragma unroll
        for (int tt = 0; tt < 8; tt++) warpoff[tt][warp] = __popc(masks[tt]);
    }
    __syncthreads();
    if (threadIdx.x < 8) {
        int tt = threadIdx.x, tot = 0;
#pragma unroll
        for (int w2 = 0; w2 < 8; w2++) { int v = warpoff[tt][w2]; warpoff[tt][w2] = tot; tot += v; }
        blockbase[tt] = tot ? atomicAdd(&d_cnt[tt], tot) : 0;
    }
    __syncthreads();
#pragma unroll
    for (int tt = 0; tt < 8; tt++) {
        if (act[tt]) {
            int rank = __popc(masks[tt] & ((1u << lane) - 1u));
            int pos  = blockbase[tt] + warpoff[tt][warp] + rank;
            d_pairs[tt][pos] = make_int2(gid, nbr[tt]);
        }
    }
}

// ---------------- center tap: 128x64 tile, 8x8 register blocking ----------------
// 128 threads as 16 (point) x 8 (k); thread computes 8 points x 8 ks.
// Per c: 2 LDS.128 feat + 2 LDS.128 wgt -> 64 FFMA.
__global__ __launch_bounds__(128) void center_kernel(
        const float* __restrict__ feat, const float* __restrict__ bias,
        float* __restrict__ out, int n) {
    __shared__ float wsm[4096];       // [c][k]
    __shared__ float fs[64 * 128];    // [c][p]
    int t = threadIdx.x;
    int base = blockIdx.x * 128;

    const float4* wsrc = (const float4*)(d_wT + 4 * 4096);
#pragma unroll
    for (int i = 0; i < 8; i++) ((float4*)wsm)[t + i * 128] = wsrc[t + i * 128];

    int row = base + t;
    if (row < n) {
        const float4* fr = (const float4*)(feat + row * 64);
#pragma unroll
        for (int i = 0; i < 16; i++) {
            float4 v = fr[i];
            fs[(4 * i + 0) * 128 + t] = v.x;
            fs[(4 * i + 1) * 128 + t] = v.y;
            fs[(4 * i + 2) * 128 + t] = v.z;
            fs[(4 * i + 3) * 128 + t] = v.w;
        }
    } else {
#pragma unroll
        for (int i = 0; i < 64; i++) fs[i * 128 + t] = 0.f;
    }
    __syncthreads();

    int tr = t >> 3, tc = t & 7;
    const float* fbase = fs + tr * 8;
    const float* wbase = wsm + tc * 8;
    float acc[8][8];
#pragma unroll
    for (int i = 0; i < 8; i++)
#pragma unroll
        for (int j = 0; j < 8; j++) acc[i][j] = 0.f;

#pragma unroll 4
    for (int c = 0; c < 64; c++) {
        float4 f0 = *(const float4*)(fbase + c * 128);
        float4 f1 = *(const float4*)(fbase + c * 128 + 4);
        float4 w0 = *(const float4*)(wbase + c * 64);
        float4 w1 = *(const float4*)(wbase + c * 64 + 4);
        float fv[8] = {f0.x, f0.y, f0.z, f0.w, f1.x, f1.y, f1.z, f1.w};
        float wv[8] = {w0.x, w0.y, w0.z, w0.w, w1.x, w1.y, w1.z, w1.w};
#pragma unroll
        for (int pp = 0; pp < 8; pp++)
#pragma unroll
            for (int kk = 0; kk < 8; kk++) acc[pp][kk] += fv[pp] * wv[kk];
    }

    float4 b0 = *(const float4*)(bias + tc * 8);
    float4 b1 = *(const float4*)(bias + tc * 8 + 4);
#pragma unroll
    for (int pp = 0; pp < 8; pp++) {
        int orow = base + tr * 8 + pp;
        if (orow < n) {
            float* o = out + orow * 64 + tc * 8;
            ((float4*)o)[0] = make_float4(acc[pp][0] + b0.x, acc[pp][1] + b0.y,
                                          acc[pp][2] + b0.z, acc[pp][3] + b0.w);
            ((float4*)o)[1] = make_float4(acc[pp][4] + b1.x, acc[pp][5] + b1.y,
                                          acc[pp][6] + b1.z, acc[pp][7] + b1.w);
        }
    }
}

// ---------------- off-center taps: pair-list GEMM, red.v4 accumulate ----------------
__global__ __launch_bounds__(128) void tap_kernel(
        const float* __restrict__ feat, float* __restrict__ out) {
    int tap  = blockIdx.y;
    int cnt  = d_cnt[tap];
    int base = blockIdx.x * 128;
    if (base >= cnt) return;

    __shared__ float wsm[4096];
    __shared__ float fs[64 * 128];
    int t = threadIdx.x;

    int wtap = tap + (tap >= 4 ? 1 : 0);
    const float4* wsrc = (const float4*)(d_wT + wtap * 4096);
#pragma unroll
    for (int i = 0; i < 8; i++) ((float4*)wsm)[t + i * 128] = wsrc[t + i * 128];

    int idx = base + t;
    if (idx < cnt) {
        int in = d_pairs[tap][idx].y;
        const float4* fr = (const float4*)(feat + in * 64);
#pragma unroll
        for (int i = 0; i < 16; i++) {
            float4 v = fr[i];
            fs[(4 * i + 0) * 128 + t] = v.x;
            fs[(4 * i + 1) * 128 + t] = v.y;
            fs[(4 * i + 2) * 128 + t] = v.z;
            fs[(4 * i + 3) * 128 + t] = v.w;
        }
    }
    __syncthreads();

    int tr = t >> 3, tc = t & 7;
    const float* fbase = fs + tr * 8;
    const float* wbase = wsm + tc * 8;
    float acc[8][8];
#pragma unroll
    for (int i = 0; i < 8; i++)
#pragma unroll
        for (int j = 0; j < 8; j++) acc[i][j] = 0.f;

#pragma unroll 4
    for (int c = 0; c < 64; c++) {
        float4 f0 = *(const float4*)(fbase + c * 128);
        float4 f1 = *(const float4*)(fbase + c * 128 + 4);
        float4 w0 = *(const float4*)(wbase + c * 64);
        float4 w1 = *(const float4*)(wbase + c * 64 + 4);
        float fv[8] = {f0.x, f0.y, f0.z, f0.w, f1.x, f1.y, f1.z, f1.w};
        float wv[8] = {w0.x, w0.y, w0.z, w0.w, w1.x, w1.y, w1.z, w1.w};
#pragma unroll
        for (int pp = 0; pp < 8; pp++)
#pragma unroll
            for (int kk = 0; kk < 8; kk++) acc[pp][kk] += fv[pp] * wv[kk];
    }

#pragma unroll
    for (int pp = 0; pp < 8; pp++) {
        int idx2 = base + tr * 8 + pp;
        if (idx2 < cnt) {
            int orow = d_pairs[tap][idx2].x;
            float* o = out + orow * 64 + tc * 8;
            asm volatile("red.global.add.v4.f32 [%0], {%1, %2, %3, %4};"
                         :: "l"(o), "f"(acc[pp][0]), "f"(acc[pp][1]),
                            "f"(acc[pp][2]), "f"(acc[pp][3]) : "memory");
            asm volatile("red.global.add.v4.f32 [%0], {%1, %2, %3, %4};"
                         :: "l"(o + 4), "f"(acc[pp][4]), "f"(acc[pp][5]),
                            "f"(acc[pp][6]), "f"(acc[pp][7]) : "memory");
        }
    }
}

// ---------------- launch ----------------
extern "C" void kernel_launch(void* const* d_in, const int* in_sizes, int n_in,
                              void* d_out, int out_size) {
    const float* feat = (const float*)d_in[0];
    const int*   idxs = (const int*)d_in[1];
    const float* wgt  = (const float*)d_in[2];
    const float* bias = (const float*)d_in[3];
    float* out = (float*)d_out;
    int n = in_sizes[0] / 64;

    wprep_kernel<<<144, 256>>>(wgt);
    scatter_kernel<<<(n + 255) / 256, 256>>>(idxs, n);
    build_kernel<<<(n + 255) / 256, 256>>>(idxs, n);
    center_kernel<<<(n + 127) / 128, 128>>>(feat, bias, out, n);
    dim3 g4((n + 127) / 128, 8, 1);
    tap_kernel<<<g4, 128>>>(feat, out);
}

// round 3
// speedup vs baseline: 1.7872x; 1.0204x over previous
#include <cuda_runtime.h>

// ---------------------------------------------------------------------------
// Submanifold sparse conv2d, B=4, H=W=1024, C=K=64, 3x3, stride1/pad1/dil1.
//
// Pipeline:
//   wprep   : weight [K][3][3][C] -> d_wT [tap][c][k]
//   scatter : d_grid[flat] = n+1  (0 = empty; static zero-init), zero counters
//   build   : per-point neighbor probes -> 8 compacted per-tap (out,in) lists
//   center  : dense 128x64 register-blocked GEMM + bias (packed f32x2 FMA)
//   tap     : pair-list 128x64 register-blocked GEMM, red.v4 accumulate
// ---------------------------------------------------------------------------

#define HH 1024
#define WW 1024
#define NMAX 400000

typedef unsigned long long u64;

// Packed fp32x2 FMA: d = a * b + d (element-wise, exact fp32)
#define FMA2(d, a, b) \
    asm("fma.rn.f32x2 %0, %1, %2, %0;" : "+l"(d) : "l"(a), "l"(b))
#define DUP2(d, f) \
    asm("mov.b64 %0, {%1, %1};" : "=l"(d) : "f"(f))
#define UNPK2(lo, hi, v) \
    asm("mov.b64 {%0, %1}, %2;" : "=f"(lo), "=f"(hi) : "l"(v))

__device__ int    d_grid[1 << 22];        // stores row+1, 0 = empty (zero-init)
__device__ int2   d_pairs[8][NMAX];       // per off-center tap: (out_row, in_row)
__device__ int    d_cnt[8];
__device__ float  d_wT[9 * 64 * 64];      // [tap][c][k]

// ---------------- weight transpose: [k][tap][c] -> [tap][c][k] ----------------
__global__ void wprep_kernel(const float* __restrict__ wgt) {
    int idx = blockIdx.x * 256 + threadIdx.x;
    if (idx < 9 * 64 * 64) {
        int k = idx & 63, c = (idx >> 6) & 63, tap = idx >> 12;
        d_wT[idx] = wgt[((k * 9 + tap) << 6) + c];
    }
}

// ---------------- scatter rows into dense hash grid ----------------
__global__ void scatter_kernel(const int* __restrict__ idxs, int n) {
    int gid = blockIdx.x * 256 + threadIdx.x;
    if (gid < 8) d_cnt[gid] = 0;
    if (gid < n) {
        int b = idxs[gid * 3], h = idxs[gid * 3 + 1], w = idxs[gid * 3 + 2];
        d_grid[(b << 20) + (h << 10) + w] = gid + 1;
    }
}

// ---------------- build compacted per-tap pair lists ----------------
__global__ void build_kernel(const int* __restrict__ idxs, int n) {
    int gid  = blockIdx.x * 256 + threadIdx.x;
    int warp = threadIdx.x >> 5, lane = threadIdx.x & 31;
    __shared__ int warpoff[8][8];
    __shared__ int blockbase[8];

    bool valid = gid < n;
    int b = 0, h = 0, w = 0;
    if (valid) { b = idxs[gid * 3]; h = idxs[gid * 3 + 1]; w = idxs[gid * 3 + 2]; }

    int nbr[8];
    bool act[8];
    unsigned masks[8];
#pragma unroll
    for (int tt = 0; tt < 8; tt++) {
        int wt = tt + (tt >= 4 ? 1 : 0);       // skip center (tap 4)
        int r = wt / 3, s = wt - r * 3;
        int hi = h + r - 1, wi = w + s - 1;
        bool ib = valid && ((unsigned)hi < HH) && ((unsigned)wi < WW);
        int g = 0;
        if (ib) g = d_grid[(b << 20) + (hi << 10) + wi];
        nbr[tt] = g - 1;
        act[tt] = g > 0;
        masks[tt] = __ballot_sync(0xffffffffu, act[tt]);
    }
    if (lane == 0) {
#pragma unroll
        for (int tt = 0; tt < 8; tt++) warpoff[tt][warp] = __popc(masks[tt]);
    }
    __syncthreads();
    if (threadIdx.x < 8) {
        int tt = threadIdx.x, tot = 0;
#pragma unroll
        for (int w2 = 0; w2 < 8; w2++) { int v = warpoff[tt][w2]; warpoff[tt][w2] = tot; tot += v; }
        blockbase[tt] = tot ? atomicAdd(&d_cnt[tt], tot) : 0;
    }
    __syncthreads();
#pragma unroll
    for (int tt = 0; tt < 8; tt++) {
        if (act[tt]) {
            int rank = __popc(masks[tt] & ((1u << lane) - 1u));
            int pos  = blockbase[tt] + warpoff[tt][warp] + rank;
            d_pairs[tt][pos] = make_int2(gid, nbr[tt]);
        }
    }
}

// ---------------- center tap: 128x64 tile, 8x8 blocking, f32x2 FMA ----------------
__global__ __launch_bounds__(128) void center_kernel(
        const float* __restrict__ feat, const float* __restrict__ bias,
        float* __restrict__ out, int n) {
    __shared__ float wsm[4096];       // [c][k]
    __shared__ float fs[64 * 128];    // [c][p]
    int t = threadIdx.x;
    int base = blockIdx.x * 128;

    const float4* wsrc = (const float4*)(d_wT + 4 * 4096);
#pragma unroll
    for (int i = 0; i < 8; i++) ((float4*)wsm)[t + i * 128] = wsrc[t + i * 128];

    int row = base + t;
    if (row < n) {
        const float4* fr = (const float4*)(feat + row * 64);
#pragma unroll
        for (int i = 0; i < 16; i++) {
            float4 v = fr[i];
            fs[(4 * i + 0) * 128 + t] = v.x;
            fs[(4 * i + 1) * 128 + t] = v.y;
            fs[(4 * i + 2) * 128 + t] = v.z;
            fs[(4 * i + 3) * 128 + t] = v.w;
        }
    } else {
#pragma unroll
        for (int i = 0; i < 64; i++) fs[i * 128 + t] = 0.f;
    }
    __syncthreads();

    int tr = t >> 3, tc = t & 7;
    const float* fbase = fs + tr * 8;
    const float* wbase = wsm + tc * 8;
    u64 acc[8][4];
#pragma unroll
    for (int i = 0; i < 8; i++)
#pragma unroll
        for (int j = 0; j < 4; j++) acc[i][j] = 0ull;

#pragma unroll 4
    for (int c = 0; c < 64; c++) {
        float4 f0 = *(const float4*)(fbase + c * 128);
        float4 f1 = *(const float4*)(fbase + c * 128 + 4);
        const u64* wr = (const u64*)(wbase + c * 64);
        u64 w0 = wr[0], w1 = wr[1], w2 = wr[2], w3 = wr[3];
        float fv[8] = {f0.x, f0.y, f0.z, f0.w, f1.x, f1.y, f1.z, f1.w};
        u64 fd[8];
#pragma unroll
        for (int pp = 0; pp < 8; pp++) DUP2(fd[pp], fv[pp]);
#pragma unroll
        for (int pp = 0; pp < 8; pp++) {
            FMA2(acc[pp][0], fd[pp], w0);
            FMA2(acc[pp][1], fd[pp], w1);
            FMA2(acc[pp][2], fd[pp], w2);
            FMA2(acc[pp][3], fd[pp], w3);
        }
    }

    float4 b0 = *(const float4*)(bias + tc * 8);
    float4 b1 = *(const float4*)(bias + tc * 8 + 4);
    float bb[8] = {b0.x, b0.y, b0.z, b0.w, b1.x, b1.y, b1.z, b1.w};
#pragma unroll
    for (int pp = 0; pp < 8; pp++) {
        int orow = base + tr * 8 + pp;
        if (orow < n) {
            float r[8];
#pragma unroll
            for (int j = 0; j < 4; j++) UNPK2(r[2 * j], r[2 * j + 1], acc[pp][j]);
            float* o = out + orow * 64 + tc * 8;
            ((float4*)o)[0] = make_float4(r[0] + bb[0], r[1] + bb[1], r[2] + bb[2], r[3] + bb[3]);
            ((float4*)o)[1] = make_float4(r[4] + bb[4], r[5] + bb[5], r[6] + bb[6], r[7] + bb[7]);
        }
    }
}

// ---------------- off-center taps: pair-list GEMM, f32x2 FMA, red.v4 ----------------
__global__ __launch_bounds__(128) void tap_kernel(
        const float* __restrict__ feat, float* __restrict__ out) {
    int tap  = blockIdx.y;
    int cnt  = d_cnt[tap];
    int base = blockIdx.x * 128;
    if (base >= cnt) return;

    __shared__ float wsm[4096];
    __shared__ float fs[64 * 128];
    int t = threadIdx.x;

    int wtap = tap + (tap >= 4 ? 1 : 0);
    const float4* wsrc = (const float4*)(d_wT + wtap * 4096);
#pragma unroll
    for (int i = 0; i < 8; i++) ((float4*)wsm)[t + i * 128] = wsrc[t + i * 128];

    int idx = base + t;
    if (idx < cnt) {
        int in = d_pairs[tap][idx].y;
        const float4* fr = (const float4*)(feat + in * 64);
#pragma unroll
        for (int i = 0; i < 16; i++) {
            float4 v = fr[i];
            fs[(4 * i + 0) * 128 + t] = v.x;
            fs[(4 * i + 1) * 128 + t] = v.y;
            fs[(4 * i + 2) * 128 + t] = v.z;
            fs[(4 * i + 3) * 128 + t] = v.w;
        }
    }
    __syncthreads();

    int tr = t >> 3, tc = t & 7;
    const float* fbase = fs + tr * 8;
    const float* wbase = wsm + tc * 8;
    u64 acc[8][4];
#pragma unroll
    for (int i = 0; i < 8; i++)
#pragma unroll
        for (int j = 0; j < 4; j++) acc[i][j] = 0ull;

#pragma unroll 4
    for (int c = 0; c < 64; c++) {
        float4 f0 = *(const float4*)(fbase + c * 128);
        float4 f1 = *(const float4*)(fbase + c * 128 + 4);
        const u64* wr = (const u64*)(wbase + c * 64);
        u64 w0 = wr[0], w1 = wr[1], w2 = wr[2], w3 = wr[3];
        float fv[8] = {f0.x, f0.y, f0.z, f0.w, f1.x, f1.y, f1.z, f1.w};
        u64 fd[8];
#pragma unroll
        for (int pp = 0; pp < 8; pp++) DUP2(fd[pp], fv[pp]);
#pragma unroll
        for (int pp = 0; pp < 8; pp++) {
            FMA2(acc[pp][0], fd[pp], w0);
            FMA2(acc[pp][1], fd[pp], w1);
            FMA2(acc[pp][2], fd[pp], w2);
            FMA2(acc[pp][3], fd[pp], w3);
        }
    }

#pragma unroll
    for (int pp = 0; pp < 8; pp++) {
        int idx2 = base + tr * 8 + pp;
        if (idx2 < cnt) {
            int orow = d_pairs[tap][idx2].x;
            float r[8];
#pragma unroll
            for (int j = 0; j < 4; j++) UNPK2(r[2 * j], r[2 * j + 1], acc[pp][j]);
            float* o = out + orow * 64 + tc * 8;
            asm volatile("red.global.add.v4.f32 [%0], {%1, %2, %3, %4};"
                         :: "l"(o), "f"(r[0]), "f"(r[1]), "f"(r[2]), "f"(r[3]) : "memory");
            asm volatile("red.global.add.v4.f32 [%0], {%1, %2, %3, %4};"
                         :: "l"(o + 4), "f"(r[4]), "f"(r[5]), "f"(r[6]), "f"(r[7]) : "memory");
        }
    }
}

// ---------------- launch ----------------
extern "C" void kernel_launch(void* const* d_in, const int* in_sizes, int n_in,
                              void* d_out, int out_size) {
    const float* feat = (const float*)d_in[0];
    const int*   idxs = (const int*)d_in[1];
    const float* wgt  = (const float*)d_in[2];
    const float* bias = (const float*)d_in[3];
    float* out = (float*)d_out;
    int n = in_sizes[0] / 64;

    wprep_kernel<<<144, 256>>>(wgt);
    scatter_kernel<<<(n + 255) / 256, 256>>>(idxs, n);
    build_kernel<<<(n + 255) / 256, 256>>>(idxs, n);
    center_kernel<<<(n + 127) / 128, 128>>>(feat, bias, out, n);
    dim3 g4((n + 127) / 128, 8, 1);
    tap_kernel<<<g4, 128>>>(feat, out);
}

// round 7
// speedup vs baseline: 2.2073x; 1.2351x over previous
#include <cuda_runtime.h>
#include <cuda_bf16.h>
#include <cstdint>

// ---------------------------------------------------------------------------
// Submanifold sparse conv2d, B=4, H=W=1024, C=K=64, 3x3 via legacy bf16
// mma.sync (m16n8k16) with 2-term hi/lo split, 3-pass compensation.
//
//   wprep   : weight -> per-tap packed bf16 hi/lo smem images [c][kout]
//   scatter : d_grid[flat] = n+1
//   build   : compacted per-tap (out,in) pair lists
//   center  : dense 128x64x64 bf16-mma tiles + bias, direct store
//   tap     : gathered 128x64x64 bf16-mma tiles, red.v2 scatter
// ---------------------------------------------------------------------------

typedef unsigned int u32;

#define HH 1024
#define WW 1024
#define NMAX 400000
#define RS  72           // padded row stride (bf16 elems) = 144 B
#define RSB 144

__device__ int  d_grid[1 << 22];          // row+1, 0 = empty (zero-init)
__device__ int2 d_pairs[8][NMAX];
__device__ int  d_cnt[8];
__device__ __nv_bfloat16 d_wB[9][2][64][RS];   // [tap][hi/lo][c][kout] smem image

// smem byte offsets
#define AHI 0
#define ALO (128 * RSB)           // 18432
#define BHI (2 * 128 * RSB)       // 36864
#define BLO (BHI + 64 * RSB)      // 46080
#define PRS (BLO + 64 * RSB)      // 55296
#define SMEMB (PRS + 128 * 8)     // 56320

__device__ __forceinline__ u32 smem_u32(const void* p) {
    u32 a; asm("{ .reg .u64 t; cvta.to.shared.u64 t, %1; cvt.u32.u64 %0, t; }" : "=r"(a) : "l"(p));
    return a;
}
// pack two floats to bf16x2: low half = first elem, high half = second elem
__device__ __forceinline__ u32 pack_bf(float lo_elem, float hi_elem) {
    u32 r; asm("cvt.rn.bf16x2.f32 %0, %1, %2;" : "=r"(r) : "f"(hi_elem), "f"(lo_elem));
    return r;
}
#define LDSM4(r0, r1, r2, r3, addr)                                            \
    asm volatile("ldmatrix.sync.aligned.m8n8.x4.shared.b16 {%0,%1,%2,%3}, [%4];" \
        : "=r"(r0), "=r"(r1), "=r"(r2), "=r"(r3) : "r"(addr))
#define LDSM4T(r0, r1, r2, r3, addr)                                           \
    asm volatile("ldmatrix.sync.aligned.m8n8.x4.trans.shared.b16 {%0,%1,%2,%3}, [%4];" \
        : "=r"(r0), "=r"(r1), "=r"(r2), "=r"(r3) : "r"(addr))

__device__ __forceinline__ void mma16816(float c[4], const u32 a[4], u32 b0, u32 b1) {
    asm volatile("mma.sync.aligned.m16n8k16.row.col.f32.bf16.bf16.f32 "
        "{%0,%1,%2,%3}, {%4,%5,%6,%7}, {%8,%9}, {%0,%1,%2,%3};"
        : "+f"(c[0]), "+f"(c[1]), "+f"(c[2]), "+f"(c[3])
        : "r"(a[0]), "r"(a[1]), "r"(a[2]), "r"(a[3]), "r"(b0), "r"(b1));
}

// ---------------- weight prep: bf16 hi/lo packed image ----------------
__global__ void wprep_kernel(const float* __restrict__ wgt) {
    int idx = blockIdx.x * 256 + threadIdx.x;
    if (idx >= 9 * 64 * 64) return;
    int kout = idx & 63, c = (idx >> 6) & 63, tap = idx >> 12;
    float w = wgt[(kout * 9 + tap) * 64 + c];
    __nv_bfloat16 hb = __float2bfloat16_rn(w);
    float hf = __bfloat162float(hb);
    d_wB[tap][0][c][kout] = hb;
    d_wB[tap][1][c][kout] = __float2bfloat16_rn(w - hf);
}

// ---------------- scatter ----------------
__global__ void scatter_kernel(const int* __restrict__ idxs, int n) {
    int gid = blockIdx.x * 256 + threadIdx.x;
    if (gid < 8) d_cnt[gid] = 0;
    if (gid < n) {
        int b = idxs[gid * 3], h = idxs[gid * 3 + 1], w = idxs[gid * 3 + 2];
        d_grid[(b << 20) + (h << 10) + w] = gid + 1;
    }
}

// ---------------- build pair lists ----------------
__global__ void build_kernel(const int* __restrict__ idxs, int n) {
    int gid  = blockIdx.x * 256 + threadIdx.x;
    int warp = threadIdx.x >> 5, lane = threadIdx.x & 31;
    __shared__ int warpoff[8][8];
    __shared__ int blockbase[8];

    bool valid = gid < n;
    int b = 0, h = 0, w = 0;
    if (valid) { b = idxs[gid * 3]; h = idxs[gid * 3 + 1]; w = idxs[gid * 3 + 2]; }

    int nbr[8]; bool act[8]; unsigned masks[8];
#pragma unroll
    for (int tt = 0; tt < 8; tt++) {
        int wt = tt + (tt >= 4 ? 1 : 0);
        int r = wt / 3, s = wt - r * 3;
        int hi = h + r - 1, wi = w + s - 1;
        bool ib = valid && ((unsigned)hi < HH) && ((unsigned)wi < WW);
        int g = 0;
        if (ib) g = d_grid[(b << 20) + (hi << 10) + wi];
        nbr[tt] = g - 1; act[tt] = g > 0;
        masks[tt] = __ballot_sync(0xffffffffu, act[tt]);
    }
    if (lane == 0)
#pragma unroll
        for (int tt = 0; tt < 8; tt++) warpoff[tt][warp] = __popc(masks[tt]);
    __syncthreads();
    if (threadIdx.x < 8) {
        int tt = threadIdx.x, tot = 0;
#pragma unroll
        for (int w2 = 0; w2 < 8; w2++) { int v = warpoff[tt][w2]; warpoff[tt][w2] = tot; tot += v; }
        blockbase[tt] = tot ? atomicAdd(&d_cnt[tt], tot) : 0;
    }
    __syncthreads();
#pragma unroll
    for (int tt = 0; tt < 8; tt++) {
        if (act[tt]) {
            int rank = __popc(masks[tt] & ((1u << lane) - 1u));
            d_pairs[tt][blockbase[tt] + warpoff[tt][warp] + rank] = make_int2(gid, nbr[tt]);
        }
    }
}

// ---------------- shared helpers for the MMA kernels ----------------
// stage one feature row half (32 cols) as hi/lo bf16 into padded smem
__device__ __forceinline__ void stage_row(char* smc, int row, int h, const float4* fr4, bool zero) {
#pragma unroll
    for (int j = 0; j < 4; j++) {
        float4 v0 = make_float4(0.f, 0.f, 0.f, 0.f), v1 = v0;
        if (!zero) { v0 = fr4[8 * h + 2 * j]; v1 = fr4[8 * h + 2 * j + 1]; }
        float x[8] = {v0.x, v0.y, v0.z, v0.w, v1.x, v1.y, v1.z, v1.w};
        u32 hi[4], lo[4];
#pragma unroll
        for (int e = 0; e < 4; e++) {
            float a = x[2 * e], b = x[2 * e + 1];
            float ha = __bfloat162float(__float2bfloat16_rn(a));
            float hb = __bfloat162float(__float2bfloat16_rn(b));
            hi[e] = pack_bf(ha, hb);
            lo[e] = pack_bf(a - ha, b - hb);
        }
        int off = row * RSB + h * 64 + j * 16;
        *(uint4*)(smc + AHI + off) = make_uint4(hi[0], hi[1], hi[2], hi[3]);
        *(uint4*)(smc + ALO + off) = make_uint4(lo[0], lo[1], lo[2], lo[3]);
    }
}

// compute the 128x64 tile: warp (wm, wn) -> c[2][4][4]
__device__ __forceinline__ void compute_tile(u32 sb, int lane, int m0, int n0w, float c[2][4][4]) {
    u32 aBase = sb + AHI + (u32)(m0 + (lane & 15)) * RSB + (u32)(lane >> 4) * 16;
    u32 bBase = sb + BHI + (u32)(lane & 15) * RSB + (u32)(lane >> 4) * 16;
#pragma unroll
    for (int ks = 0; ks < 4; ks++) {
        int k0 = ks * 16;
        u32 ah[2][4], al[2][4], bh[8], bl[8];
        LDSM4(ah[0][0], ah[0][1], ah[0][2], ah[0][3], aBase + k0 * 2);
        LDSM4(ah[1][0], ah[1][1], ah[1][2], ah[1][3], aBase + k0 * 2 + 16 * RSB);
        LDSM4(al[0][0], al[0][1], al[0][2], al[0][3], aBase + (ALO - AHI) + k0 * 2);
        LDSM4(al[1][0], al[1][1], al[1][2], al[1][3], aBase + (ALO - AHI) + k0 * 2 + 16 * RSB);
        LDSM4T(bh[0], bh[1], bh[2], bh[3], bBase + k0 * RSB + n0w * 2);
        LDSM4T(bh[4], bh[5], bh[6], bh[7], bBase + k0 * RSB + (n0w + 16) * 2);
        LDSM4T(bl[0], bl[1], bl[2], bl[3], bBase + (BLO - BHI) + k0 * RSB + n0w * 2);
        LDSM4T(bl[4], bl[5], bl[6], bl[7], bBase + (BLO - BHI) + k0 * RSB + (n0w + 16) * 2);
#pragma unroll
        for (int mi = 0; mi < 2; mi++)
#pragma unroll
            for (int nj = 0; nj < 4; nj++) {
                mma16816(c[mi][nj], ah[mi], bh[2 * nj], bh[2 * nj + 1]);
                mma16816(c[mi][nj], ah[mi], bl[2 * nj], bl[2 * nj + 1]);
                mma16816(c[mi][nj], al[mi], bh[2 * nj], bh[2 * nj + 1]);
            }
    }
}

// ---------------- center: dense bf16-mma tiles + bias ----------------
__global__ __launch_bounds__(256) void center_kernel(
        const float* __restrict__ feat, const float* __restrict__ bias,
        float* __restrict__ out, int nn) {
    extern __shared__ char smc[];
    u32 sb = smem_u32(smc);
    int t = threadIdx.x, lane = t & 31, wid = t >> 5;
    int tile = blockIdx.x;
    int gbase = tile * 128;

    { // copy weight image (center tap 4): 2*64*RS bf16 = 18432 B
        const uint4* src = (const uint4*)d_wB[4];
        uint4* dst = (uint4*)(smc + BHI);
#pragma unroll
        for (int i = 0; i < 5; i++) {
            int idx = t + i * 256;
            if (idx < 1152) dst[idx] = src[idx];
        }
    }
    { // stage A
        int row = t >> 1, h = t & 1;
        int g = gbase + row;
        bool zero = g >= nn;
        const float4* fr4 = (const float4*)(feat + (size_t)(zero ? 0 : g) * 64);
        stage_row(smc, row, h, fr4, zero);
    }
    __syncthreads();

    int m0 = (wid >> 1) * 32, n0w = (wid & 1) * 32;
    float c[2][4][4];
#pragma unroll
    for (int mi = 0; mi < 2; mi++)
#pragma unroll
        for (int nj = 0; nj < 4; nj++)
#pragma unroll
            for (int e = 0; e < 4; e++) c[mi][nj][e] = 0.f;

    compute_tile(sb, lane, m0, n0w, c);

#pragma unroll
    for (int nj = 0; nj < 4; nj++) {
        int n = n0w + nj * 8 + 2 * (lane & 3);
        float2 bv = __ldg((const float2*)(bias + n));
#pragma unroll
        for (int mi = 0; mi < 2; mi++) {
            int r0 = gbase + m0 + mi * 16 + (lane >> 2);
            int r1 = r0 + 8;
            if (r0 < nn)
                *(float2*)(out + (size_t)r0 * 64 + n) =
                    make_float2(c[mi][nj][0] + bv.x, c[mi][nj][1] + bv.y);
            if (r1 < nn)
                *(float2*)(out + (size_t)r1 * 64 + n) =
                    make_float2(c[mi][nj][2] + bv.x, c[mi][nj][3] + bv.y);
        }
    }
}

// ---------------- taps: gathered bf16-mma tiles, red.v2 scatter ----------------
__global__ __launch_bounds__(256) void tap_kernel(
        const float* __restrict__ feat, float* __restrict__ out) {
    int tap = blockIdx.y;
    int cnt = d_cnt[tap];
    int base = blockIdx.x * 128;
    if (base >= cnt) return;

    extern __shared__ char smc[];
    u32 sb = smem_u32(smc);
    int t = threadIdx.x, lane = t & 31, wid = t >> 5;
    int wtap = tap + (tap >= 4 ? 1 : 0);
    int2* prs = (int2*)(smc + PRS);

    if (t < 128) {
        int pidx = base + t;
        prs[t] = (pidx < cnt) ? d_pairs[tap][pidx] : make_int2(-1, 0);
    }
    {
        const uint4* src = (const uint4*)d_wB[wtap];
        uint4* dst = (uint4*)(smc + BHI);
#pragma unroll
        for (int i = 0; i < 5; i++) {
            int idx = t + i * 256;
            if (idx < 1152) dst[idx] = src[idx];
        }
    }
    __syncthreads();
    {
        int row = t >> 1, h = t & 1;
        int srcrow = prs[row].y;
        const float4* fr4 = (const float4*)(feat + (size_t)srcrow * 64);
        stage_row(smc, row, h, fr4, false);
    }
    __syncthreads();

    int m0 = (wid >> 1) * 32, n0w = (wid & 1) * 32;
    float c[2][4][4];
#pragma unroll
    for (int mi = 0; mi < 2; mi++)
#pragma unroll
        for (int nj = 0; nj < 4; nj++)
#pragma unroll
            for (int e = 0; e < 4; e++) c[mi][nj][e] = 0.f;

    compute_tile(sb, lane, m0, n0w, c);

#pragma unroll
    for (int mi = 0; mi < 2; mi++) {
        int lr = m0 + mi * 16 + (lane >> 2);
        int or0 = prs[lr].x;
        int or1 = prs[lr + 8].x;
#pragma unroll
        for (int nj = 0; nj < 4; nj++) {
            int n = n0w + nj * 8 + 2 * (lane & 3);
            if (or0 >= 0)
                asm volatile("red.global.add.v2.f32 [%0], {%1, %2};"
                    :: "l"(out + (size_t)or0 * 64 + n), "f"(c[mi][nj][0]), "f"(c[mi][nj][1]) : "memory");
            if (or1 >= 0)
                asm volatile("red.global.add.v2.f32 [%0], {%1, %2};"
                    :: "l"(out + (size_t)or1 * 64 + n), "f"(c[mi][nj][2]), "f"(c[mi][nj][3]) : "memory");
        }
    }
}

// ---------------- launch ----------------
extern "C" void kernel_launch(void* const* d_in, const int* in_sizes, int n_in,
                              void* d_out, int out_size) {
    const float* feat = (const float*)d_in[0];
    const int*   idxs = (const int*)d_in[1];
    const float* wgt  = (const float*)d_in[2];
    const float* bias = (const float*)d_in[3];
    float* out = (float*)d_out;
    int n = in_sizes[0] / 64;
    int ntiles = (n + 127) / 128;

    cudaFuncSetAttribute(center_kernel, cudaFuncAttributeMaxDynamicSharedMemorySize, SMEMB);
    cudaFuncSetAttribute(tap_kernel, cudaFuncAttributeMaxDynamicSharedMemorySize, SMEMB);

    wprep_kernel<<<144, 256>>>(wgt);
    scatter_kernel<<<(n + 255) / 256, 256>>>(idxs, n);
    build_kernel<<<(n + 255) / 256, 256>>>(idxs, n);
    center_kernel<<<ntiles, 256, SMEMB>>>(feat, bias, out, n);
    dim3 g4(ntiles, 8, 1);
    tap_kernel<<<g4, 256, SMEMB>>>(feat, out);
}

// round 8
// speedup vs baseline: 2.3759x; 1.0764x over previous
#include <cuda_runtime.h>
#include <cuda_bf16.h>
#include <cstdint>

// ---------------------------------------------------------------------------
// Submanifold sparse conv2d, B=4, H=W=1024, C=K=64, 3x3 via legacy bf16
// mma.sync (m16n8k16), 2-term hi/lo split, 3-pass compensation.
//
//   wprep   : weight -> mma-ready per-lane B fragment records (hi+lo packed)
//   scatter : d_grid[flat] = n+1
//   build   : compacted per-tap (out,in) pair lists
//   center  : dense 128x64x64 bf16-mma tiles + bias, direct store
//   tap     : gathered 128x64x64 bf16-mma tiles, shfl-paired red.v4 scatter
// B operands come straight from global as LDG.128 fragments (L2-resident,
// identical across blocks) -- no B smem staging, no B ldmatrix.
// ---------------------------------------------------------------------------

typedef unsigned int u32;

#define HH 1024
#define WW 1024
#define NMAX 400000
#define RS  72           // padded A row stride (bf16 elems) = 144 B
#define RSB 144

__device__ int  d_grid[1 << 22];          // row+1, 0 = empty (zero-init)
__device__ int2 d_pairs[8][NMAX];
__device__ int  d_cnt[8];
// B fragments: [tap][ks][nc][lane] -> {b0_hi, b1_hi, b0_lo, b1_lo}
__device__ uint4 d_wF[9 * 4 * 8 * 32];

// smem byte offsets (A staging only)
#define AHI 0
#define ALO (128 * RSB)           // 18432
#define ATOT (2 * 128 * RSB)      // 36864

__device__ __forceinline__ u32 smem_u32(const void* p) {
    u32 a; asm("{ .reg .u64 t; cvta.to.shared.u64 t, %1; cvt.u32.u64 %0, t; }" : "=r"(a) : "l"(p));
    return a;
}
// pack two floats to bf16x2: low half = first arg, high half = second arg
__device__ __forceinline__ u32 pack_bf(float lo_elem, float hi_elem) {
    u32 r; asm("cvt.rn.bf16x2.f32 %0, %1, %2;" : "=r"(r) : "f"(hi_elem), "f"(lo_elem));
    return r;
}
#define LDSM4(r0, r1, r2, r3, addr)                                            \
    asm volatile("ldmatrix.sync.aligned.m8n8.x4.shared.b16 {%0,%1,%2,%3}, [%4];" \
        : "=r"(r0), "=r"(r1), "=r"(r2), "=r"(r3) : "r"(addr))

__device__ __forceinline__ void mma16816(float c[4], const u32 a[4], u32 b0, u32 b1) {
    asm volatile("mma.sync.aligned.m16n8k16.row.col.f32.bf16.bf16.f32 "
        "{%0,%1,%2,%3}, {%4,%5,%6,%7}, {%8,%9}, {%0,%1,%2,%3};"
        : "+f"(c[0]), "+f"(c[1]), "+f"(c[2]), "+f"(c[3])
        : "r"(a[0]), "r"(a[1]), "r"(a[2]), "r"(a[3]), "r"(b0), "r"(b1));
}

// ---------------- weight prep: mma-ready B fragment records ----------------
// mma.m16n8k16 B fragment: lane l holds b0 = {k0, k0+1}, b1 = {k0+8, k0+9}
// at n = l/4, where k0 = 2*(l%4) within the 16-wide kstep.
__global__ void wprep_kernel(const float* __restrict__ wgt) {
    int idx = blockIdx.x * 256 + threadIdx.x;
    if (idx >= 9 * 4 * 8 * 32) return;
    int lane = idx & 31, nc = (idx >> 5) & 7, ks = (idx >> 8) & 3, tap = idx >> 10;
    int n  = nc * 8 + (lane >> 2);          // kout
    int k0 = ks * 16 + 2 * (lane & 3);      // c (input channel)
    const float* wr = wgt + (n * 9 + tap) * 64;
    float w00 = wr[k0], w01 = wr[k0 + 1], w10 = wr[k0 + 8], w11 = wr[k0 + 9];
    float h00 = __bfloat162float(__float2bfloat16_rn(w00));
    float h01 = __bfloat162float(__float2bfloat16_rn(w01));
    float h10 = __bfloat162float(__float2bfloat16_rn(w10));
    float h11 = __bfloat162float(__float2bfloat16_rn(w11));
    uint4 rec;
    rec.x = pack_bf(h00, h01);
    rec.y = pack_bf(h10, h11);
    rec.z = pack_bf(w00 - h00, w01 - h01);
    rec.w = pack_bf(w10 - h10, w11 - h11);
    d_wF[idx] = rec;
}

// ---------------- scatter ----------------
__global__ void scatter_kernel(const int* __restrict__ idxs, int n) {
    int gid = blockIdx.x * 256 + threadIdx.x;
    if (gid < 8) d_cnt[gid] = 0;
    if (gid < n) {
        int b = idxs[gid * 3], h = idxs[gid * 3 + 1], w = idxs[gid * 3 + 2];
        d_grid[(b << 20) + (h << 10) + w] = gid + 1;
    }
}

// ---------------- build pair lists ----------------
__global__ void build_kernel(const int* __restrict__ idxs, int n) {
    int gid  = blockIdx.x * 256 + threadIdx.x;
    int warp = threadIdx.x >> 5, lane = threadIdx.x & 31;
    __shared__ int warpoff[8][8];
    __shared__ int blockbase[8];

    bool valid = gid < n;
    int b = 0, h = 0, w = 0;
    if (valid) { b = idxs[gid * 3]; h = idxs[gid * 3 + 1]; w = idxs[gid * 3 + 2]; }

    int nbr[8]; bool act[8]; unsigned masks[8];
#pragma unroll
    for (int tt = 0; tt < 8; tt++) {
        int wt = tt + (tt >= 4 ? 1 : 0);
        int r = wt / 3, s = wt - r * 3;
        int hi = h + r - 1, wi = w + s - 1;
        bool ib = valid && ((unsigned)hi < HH) && ((unsigned)wi < WW);
        int g = 0;
        if (ib) g = d_grid[(b << 20) + (hi << 10) + wi];
        nbr[tt] = g - 1; act[tt] = g > 0;
        masks[tt] = __ballot_sync(0xffffffffu, act[tt]);
    }
    if (lane == 0)
#pragma unroll
        for (int tt = 0; tt < 8; tt++) warpoff[tt][warp] = __popc(masks[tt]);
    __syncthreads();
    if (threadIdx.x < 8) {
        int tt = threadIdx.x, tot = 0;
#pragma unroll
        for (int w2 = 0; w2 < 8; w2++) { int v = warpoff[tt][w2]; warpoff[tt][w2] = tot; tot += v; }
        blockbase[tt] = tot ? atomicAdd(&d_cnt[tt], tot) : 0;
    }
    __syncthreads();
#pragma unroll
    for (int tt = 0; tt < 8; tt++) {
        if (act[tt]) {
            int rank = __popc(masks[tt] & ((1u << lane) - 1u));
            d_pairs[tt][blockbase[tt] + warpoff[tt][warp] + rank] = make_int2(gid, nbr[tt]);
        }
    }
}

// ---------------- shared helpers ----------------
// stage one feature row half (32 cols) as hi/lo bf16 into padded smem
__device__ __forceinline__ void stage_row(char* smc, int row, int h, const float4* fr4, bool zero) {
#pragma unroll
    for (int j = 0; j < 4; j++) {
        float4 v0 = make_float4(0.f, 0.f, 0.f, 0.f), v1 = v0;
        if (!zero) { v0 = fr4[8 * h + 2 * j]; v1 = fr4[8 * h + 2 * j + 1]; }
        float x[8] = {v0.x, v0.y, v0.z, v0.w, v1.x, v1.y, v1.z, v1.w};
        u32 hi[4], lo[4];
#pragma unroll
        for (int e = 0; e < 4; e++) {
            float a = x[2 * e], b = x[2 * e + 1];
            float ha = __bfloat162float(__float2bfloat16_rn(a));
            float hb = __bfloat162float(__float2bfloat16_rn(b));
            hi[e] = pack_bf(ha, hb);
            lo[e] = pack_bf(a - ha, b - hb);
        }
        int off = row * RSB + h * 64 + j * 16;
        *(uint4*)(smc + AHI + off) = make_uint4(hi[0], hi[1], hi[2], hi[3]);
        *(uint4*)(smc + ALO + off) = make_uint4(lo[0], lo[1], lo[2], lo[3]);
    }
}

// compute the 128x64 tile: warp (m0, n0w) -> c[2][4][4].
// A fragments from smem via ldmatrix; B fragments direct LDG.128 from d_wF.
__device__ __forceinline__ void compute_tile(u32 sb, int lane, int m0, int n0w,
                                             const uint4* __restrict__ wf, float c[2][4][4]) {
    u32 aBase = sb + AHI + (u32)(m0 + (lane & 15)) * RSB + (u32)(lane >> 4) * 16;
#pragma unroll
    for (int ks = 0; ks < 4; ks++) {
        int k0 = ks * 16;
        u32 ah[2][4], al[2][4];
        LDSM4(ah[0][0], ah[0][1], ah[0][2], ah[0][3], aBase + k0 * 2);
        LDSM4(ah[1][0], ah[1][1], ah[1][2], ah[1][3], aBase + k0 * 2 + 16 * RSB);
        LDSM4(al[0][0], al[0][1], al[0][2], al[0][3], aBase + (ALO - AHI) + k0 * 2);
        LDSM4(al[1][0], al[1][1], al[1][2], al[1][3], aBase + (ALO - AHI) + k0 * 2 + 16 * RSB);
#pragma unroll
        for (int nj = 0; nj < 4; nj++) {
            uint4 f = __ldg(&wf[(ks * 8 + (n0w >> 3) + nj) * 32 + lane]);
#pragma unroll
            for (int mi = 0; mi < 2; mi++) {
                mma16816(c[mi][nj], ah[mi], f.x, f.y);
                mma16816(c[mi][nj], ah[mi], f.z, f.w);
                mma16816(c[mi][nj], al[mi], f.x, f.y);
            }
        }
    }
}

// ---------------- center: dense bf16-mma tiles + bias ----------------
__global__ __launch_bounds__(256) void center_kernel(
        const float* __restrict__ feat, const float* __restrict__ bias,
        float* __restrict__ out, int nn) {
    __shared__ char smc[ATOT];
    u32 sb = smem_u32(smc);
    int t = threadIdx.x, lane = t & 31, wid = t >> 5;
    int gbase = blockIdx.x * 128;

    { // stage A
        int row = t >> 1, h = t & 1;
        int g = gbase + row;
        bool zero = g >= nn;
        const float4* fr4 = (const float4*)(feat + (size_t)(zero ? 0 : g) * 64);
        stage_row(smc, row, h, fr4, zero);
    }
    __syncthreads();

    int m0 = (wid >> 1) * 32, n0w = (wid & 1) * 32;
    const uint4* wf = d_wF + 4 * 1024;       // center tap = 4
    float c[2][4][4];
#pragma unroll
    for (int mi = 0; mi < 2; mi++)
#pragma unroll
        for (int nj = 0; nj < 4; nj++)
#pragma unroll
            for (int e = 0; e < 4; e++) c[mi][nj][e] = 0.f;

    compute_tile(sb, lane, m0, n0w, wf, c);

#pragma unroll
    for (int nj = 0; nj < 4; nj++) {
        int n = n0w + nj * 8 + 2 * (lane & 3);
        float2 bv = __ldg((const float2*)(bias + n));
#pragma unroll
        for (int mi = 0; mi < 2; mi++) {
            int r0 = gbase + m0 + mi * 16 + (lane >> 2);
            int r1 = r0 + 8;
            if (r0 < nn)
                *(float2*)(out + (size_t)r0 * 64 + n) =
                    make_float2(c[mi][nj][0] + bv.x, c[mi][nj][1] + bv.y);
            if (r1 < nn)
                *(float2*)(out + (size_t)r1 * 64 + n) =
                    make_float2(c[mi][nj][2] + bv.x, c[mi][nj][3] + bv.y);
        }
    }
}

// ---------------- taps: gathered tiles, shfl-paired red.v4 scatter ----------------
__global__ __launch_bounds__(256) void tap_kernel(
        const float* __restrict__ feat, float* __restrict__ out) {
    int tap = blockIdx.y;
    int cnt = d_cnt[tap];
    int base = blockIdx.x * 128;
    if (base >= cnt) return;

    __shared__ char smc[ATOT];
    __shared__ int2 prs[128];
    u32 sb = smem_u32(smc);
    int t = threadIdx.x, lane = t & 31, wid = t >> 5;
    int wtap = tap + (tap >= 4 ? 1 : 0);

    if (t < 128) {
        int pidx = base + t;
        prs[t] = (pidx < cnt) ? d_pairs[tap][pidx] : make_int2(-1, 0);
    }
    __syncthreads();
    {
        int row = t >> 1, h = t & 1;
        int srcrow = prs[row].y;
        const float4* fr4 = (const float4*)(feat + (size_t)srcrow * 64);
        stage_row(smc, row, h, fr4, false);
    }
    __syncthreads();

    int m0 = (wid >> 1) * 32, n0w = (wid & 1) * 32;
    const uint4* wf = d_wF + wtap * 1024;
    float c[2][4][4];
#pragma unroll
    for (int mi = 0; mi < 2; mi++)
#pragma unroll
        for (int nj = 0; nj < 4; nj++)
#pragma unroll
            for (int e = 0; e < 4; e++) c[mi][nj][e] = 0.f;

    compute_tile(sb, lane, m0, n0w, wf, c);

    // epilogue: pair lanes (l, l^1) to form 4-wide column quads -> red.v4
#pragma unroll
    for (int mi = 0; mi < 2; mi++) {
        int lr = m0 + mi * 16 + (lane >> 2);
        int or0 = prs[lr].x;          // row r      (even lanes store this)
        int or1 = prs[lr + 8].x;      // row r + 8  (odd lanes store this)
#pragma unroll
        for (int nj = 0; nj < 4; nj++) {
            float t0 = __shfl_xor_sync(0xffffffffu, c[mi][nj][0], 1);
            float t1 = __shfl_xor_sync(0xffffffffu, c[mi][nj][1], 1);
            float t2 = __shfl_xor_sync(0xffffffffu, c[mi][nj][2], 1);
            float t3 = __shfl_xor_sync(0xffffffffu, c[mi][nj][3], 1);
            int colb = n0w + nj * 8 + 4 * ((lane & 3) >> 1);
            if ((lane & 1) == 0) {
                if (or0 >= 0)
                    asm volatile("red.global.add.v4.f32 [%0], {%1, %2, %3, %4};"
                        :: "l"(out + (size_t)or0 * 64 + colb),
                           "f"(c[mi][nj][0]), "f"(c[mi][nj][1]), "f"(t0), "f"(t1) : "memory");
            } else {
                if (or1 >= 0)
                    asm volatile("red.global.add.v4.f32 [%0], {%1, %2, %3, %4};"
                        :: "l"(out + (size_t)or1 * 64 + colb),
                           "f"(t2), "f"(t3), "f"(c[mi][nj][2]), "f"(c[mi][nj][3]) : "memory");
            }
        }
    }
}

// ---------------- launch ----------------
extern "C" void kernel_launch(void* const* d_in, const int* in_sizes, int n_in,
                              void* d_out, int out_size) {
    const float* feat = (const float*)d_in[0];
    const int*   idxs = (const int*)d_in[1];
    const float* wgt  = (const float*)d_in[2];
    const float* bias = (const float*)d_in[3];
    float* out = (float*)d_out;
    int n = in_sizes[0] / 64;
    int ntiles = (n + 127) / 128;

    wprep_kernel<<<36, 256>>>(wgt);
    scatter_kernel<<<(n + 255) / 256, 256>>>(idxs, n);
    build_kernel<<<(n + 255) / 256, 256>>>(idxs, n);
    center_kernel<<<ntiles, 256>>>(feat, bias, out, n);
    dim3 g4(ntiles, 8, 1);
    tap_kernel<<<g4, 256>>>(feat, out);
}

// round 11
// speedup vs baseline: 2.5016x; 1.0529x over previous
#include <cuda_runtime.h>
#include <cuda_bf16.h>
#include <cstdint>

// ---------------------------------------------------------------------------
// Submanifold sparse conv2d, B=4, H=W=1024, C=K=64, 3x3 via legacy bf16
// mma.sync (m16n8k16), 2-term hi/lo split, 3-pass compensation.
//
//   wprep   : weight -> mma-ready per-lane B fragment records (hi+lo packed)
//   scatter : d_grid[flat] = n+1
//   build   : compacted per-tap (out,in) pair lists
//   center  : dense tiles + bias, plain store       (must complete first)
//   tap     : persistent worklist over tap tiles, red.v4 accumulate
// Ordering: center's plain stores happen-before tap's reductions via the
// stream -- do NOT fuse (fusion raced store vs red and lost updates, R10).
// ---------------------------------------------------------------------------

typedef unsigned int u32;

#define HH 1024
#define WW 1024
#define NMAX 400000
#define RS  72           // padded A row stride (bf16 elems) = 144 B
#define RSB 144

__device__ int  d_grid[1 << 22];          // row+1, 0 = empty (zero-init)
__device__ int2 d_pairs[8][NMAX];
__device__ int  d_cnt[8];
// B fragments: [tap][ks][nc][lane] -> {b0_hi, b1_hi, b0_lo, b1_lo}
__device__ uint4 d_wF[9 * 4 * 8 * 32];

// smem byte offsets (A staging only)
#define AHI 0
#define ALO (128 * RSB)           // 18432
#define ATOT (2 * 128 * RSB)      // 36864

__device__ __forceinline__ u32 smem_u32(const void* p) {
    u32 a; asm("{ .reg .u64 t; cvta.to.shared.u64 t, %1; cvt.u32.u64 %0, t; }" : "=r"(a) : "l"(p));
    return a;
}
// pack two floats to bf16x2: low half = first arg, high half = second arg
__device__ __forceinline__ u32 pack_bf(float lo_elem, float hi_elem) {
    u32 r; asm("cvt.rn.bf16x2.f32 %0, %1, %2;" : "=r"(r) : "f"(hi_elem), "f"(lo_elem));
    return r;
}
#define LDSM4(r0, r1, r2, r3, addr)                                            \
    asm volatile("ldmatrix.sync.aligned.m8n8.x4.shared.b16 {%0,%1,%2,%3}, [%4];" \
        : "=r"(r0), "=r"(r1), "=r"(r2), "=r"(r3) : "r"(addr))

__device__ __forceinline__ void mma16816(float c[4], const u32 a[4], u32 b0, u32 b1) {
    asm volatile("mma.sync.aligned.m16n8k16.row.col.f32.bf16.bf16.f32 "
        "{%0,%1,%2,%3}, {%4,%5,%6,%7}, {%8,%9}, {%0,%1,%2,%3};"
        : "+f"(c[0]), "+f"(c[1]), "+f"(c[2]), "+f"(c[3])
        : "r"(a[0]), "r"(a[1]), "r"(a[2]), "r"(a[3]), "r"(b0), "r"(b1));
}

// ---------------- weight prep: mma-ready B fragment records ----------------
__global__ void wprep_kernel(const float* __restrict__ wgt) {
    int idx = blockIdx.x * 256 + threadIdx.x;
    if (idx >= 9 * 4 * 8 * 32) return;
    int lane = idx & 31, nc = (idx >> 5) & 7, ks = (idx >> 8) & 3, tap = idx >> 10;
    int n  = nc * 8 + (lane >> 2);          // kout
    int k0 = ks * 16 + 2 * (lane & 3);      // c (input channel)
    const float* wr = wgt + (n * 9 + tap) * 64;
    float w00 = wr[k0], w01 = wr[k0 + 1], w10 = wr[k0 + 8], w11 = wr[k0 + 9];
    float h00 = __bfloat162float(__float2bfloat16_rn(w00));
    float h01 = __bfloat162float(__float2bfloat16_rn(w01));
    float h10 = __bfloat162float(__float2bfloat16_rn(w10));
    float h11 = __bfloat162float(__float2bfloat16_rn(w11));
    uint4 rec;
    rec.x = pack_bf(h00, h01);
    rec.y = pack_bf(h10, h11);
    rec.z = pack_bf(w00 - h00, w01 - h01);
    rec.w = pack_bf(w10 - h10, w11 - h11);
    d_wF[idx] = rec;
}

// ---------------- scatter ----------------
__global__ void scatter_kernel(const int* __restrict__ idxs, int n) {
    int gid = blockIdx.x * 256 + threadIdx.x;
    if (gid < 8) d_cnt[gid] = 0;
    if (gid < n) {
        int b = idxs[gid * 3], h = idxs[gid * 3 + 1], w = idxs[gid * 3 + 2];
        d_grid[(b << 20) + (h << 10) + w] = gid + 1;
    }
}

// ---------------- build pair lists ----------------
__global__ void build_kernel(const int* __restrict__ idxs, int n) {
    int gid  = blockIdx.x * 256 + threadIdx.x;
    int warp = threadIdx.x >> 5, lane = threadIdx.x & 31;
    __shared__ int warpoff[8][8];
    __shared__ int blockbase[8];

    bool valid = gid < n;
    int b = 0, h = 0, w = 0;
    if (valid) { b = idxs[gid * 3]; h = idxs[gid * 3 + 1]; w = idxs[gid * 3 + 2]; }

    int nbr[8]; bool act[8]; unsigned masks[8];
#pragma unroll
    for (int tt = 0; tt < 8; tt++) {
        int wt = tt + (tt >= 4 ? 1 : 0);
        int r = wt / 3, s = wt - r * 3;
        int hi = h + r - 1, wi = w + s - 1;
        bool ib = valid && ((unsigned)hi < HH) && ((unsigned)wi < WW);
        int g = 0;
        if (ib) g = d_grid[(b << 20) + (hi << 10) + wi];
        nbr[tt] = g - 1; act[tt] = g > 0;
        masks[tt] = __ballot_sync(0xffffffffu, act[tt]);
    }
    if (lane == 0)
#pragma unroll
        for (int tt = 0; tt < 8; tt++) warpoff[tt][warp] = __popc(masks[tt]);
    __syncthreads();
    if (threadIdx.x < 8) {
        int tt = threadIdx.x, tot = 0;
#pragma unroll
        for (int w2 = 0; w2 < 8; w2++) { int v = warpoff[tt][w2]; warpoff[tt][w2] = tot; tot += v; }
        blockbase[tt] = tot ? atomicAdd(&d_cnt[tt], tot) : 0;
    }
    __syncthreads();
#pragma unroll
    for (int tt = 0; tt < 8; tt++) {
        if (act[tt]) {
            int rank = __popc(masks[tt] & ((1u << lane) - 1u));
            d_pairs[tt][blockbase[tt] + warpoff[tt][warp] + rank] = make_int2(gid, nbr[tt]);
        }
    }
}

// ---------------- shared helpers ----------------
// stage one feature row half (32 cols) as hi/lo bf16 into padded smem
__device__ __forceinline__ void stage_row(char* smc, int row, int h, const float4* fr4, bool zero) {
#pragma unroll
    for (int j = 0; j < 4; j++) {
        float4 v0 = make_float4(0.f, 0.f, 0.f, 0.f), v1 = v0;
        if (!zero) { v0 = fr4[8 * h + 2 * j]; v1 = fr4[8 * h + 2 * j + 1]; }
        float x[8] = {v0.x, v0.y, v0.z, v0.w, v1.x, v1.y, v1.z, v1.w};
        u32 hi[4], lo[4];
#pragma unroll
        for (int e = 0; e < 4; e++) {
            float a = x[2 * e], b = x[2 * e + 1];
            float ha = __bfloat162float(__float2bfloat16_rn(a));
            float hb = __bfloat162float(__float2bfloat16_rn(b));
            hi[e] = pack_bf(ha, hb);
            lo[e] = pack_bf(a - ha, b - hb);
        }
        int off = row * RSB + h * 64 + j * 16;
        *(uint4*)(smc + AHI + off) = make_uint4(hi[0], hi[1], hi[2], hi[3]);
        *(uint4*)(smc + ALO + off) = make_uint4(lo[0], lo[1], lo[2], lo[3]);
    }
}

// compute the 128x64 tile: warp (m0, n0w) -> c[2][4][4].
// A fragments from smem via ldmatrix; B fragments direct LDG.128 from d_wF.
__device__ __forceinline__ void compute_tile(u32 sb, int lane, int m0, int n0w,
                                             const uint4* __restrict__ wf, float c[2][4][4]) {
    u32 aBase = sb + AHI + (u32)(m0 + (lane & 15)) * RSB + (u32)(lane >> 4) * 16;
#pragma unroll
    for (int ks = 0; ks < 4; ks++) {
        int k0 = ks * 16;
        u32 ah[2][4], al[2][4];
        LDSM4(ah[0][0], ah[0][1], ah[0][2], ah[0][3], aBase + k0 * 2);
        LDSM4(ah[1][0], ah[1][1], ah[1][2], ah[1][3], aBase + k0 * 2 + 16 * RSB);
        LDSM4(al[0][0], al[0][1], al[0][2], al[0][3], aBase + (ALO - AHI) + k0 * 2);
        LDSM4(al[1][0], al[1][1], al[1][2], al[1][3], aBase + (ALO - AHI) + k0 * 2 + 16 * RSB);
#pragma unroll
        for (int nj = 0; nj < 4; nj++) {
            uint4 f = __ldg(&wf[(ks * 8 + (n0w >> 3) + nj) * 32 + lane]);
#pragma unroll
            for (int mi = 0; mi < 2; mi++) {
                mma16816(c[mi][nj], ah[mi], f.x, f.y);
                mma16816(c[mi][nj], ah[mi], f.z, f.w);
                mma16816(c[mi][nj], al[mi], f.x, f.y);
            }
        }
    }
}

// ---------------- center: dense bf16-mma tiles + bias (plain store) ----------------
__global__ __launch_bounds__(256, 3) void center_kernel(
        const float* __restrict__ feat, const float* __restrict__ bias,
        float* __restrict__ out, int nn) {
    __shared__ char smc[ATOT];
    u32 sb = smem_u32(smc);
    int t = threadIdx.x, lane = t & 31, wid = t >> 5;
    int gbase = blockIdx.x * 128;

    {
        int row = t >> 1, h = t & 1;
        int g = gbase + row;
        bool zero = g >= nn;
        const float4* fr4 = (const float4*)(feat + (size_t)(zero ? 0 : g) * 64);
        stage_row(smc, row, h, fr4, zero);
    }
    __syncthreads();

    int m0 = (wid >> 1) * 32, n0w = (wid & 1) * 32;
    float c[2][4][4];
#pragma unroll
    for (int mi = 0; mi < 2; mi++)
#pragma unroll
        for (int nj = 0; nj < 4; nj++)
#pragma unroll
            for (int e = 0; e < 4; e++) c[mi][nj][e] = 0.f;

    compute_tile(sb, lane, m0, n0w, d_wF + 4 * 1024, c);

#pragma unroll
    for (int nj = 0; nj < 4; nj++) {
        int n = n0w + nj * 8 + 2 * (lane & 3);
        float2 bv = __ldg((const float2*)(bias + n));
#pragma unroll
        for (int mi = 0; mi < 2; mi++) {
            int r0 = gbase + m0 + mi * 16 + (lane >> 2);
            int r1 = r0 + 8;
            if (r0 < nn)
                *(float2*)(out + (size_t)r0 * 64 + n) =
                    make_float2(c[mi][nj][0] + bv.x, c[mi][nj][1] + bv.y);
            if (r1 < nn)
                *(float2*)(out + (size_t)r1 * 64 + n) =
                    make_float2(c[mi][nj][2] + bv.x, c[mi][nj][3] + bv.y);
        }
    }
}

// ---------------- taps: persistent worklist, shfl-paired red.v4 scatter ----------------
__global__ __launch_bounds__(256, 3) void tap_kernel(
        const float* __restrict__ feat, float* __restrict__ out) {
    __shared__ char smc[ATOT];
    __shared__ int2 prs[128];
    u32 sb = smem_u32(smc);
    int t = threadIdx.x, lane = t & 31, wid = t >> 5;
    int m0 = (wid >> 1) * 32, n0w = (wid & 1) * 32;

    // worklist prefix over the 8 tap pair-lists
    int pre[9];
    pre[0] = 0;
#pragma unroll
    for (int tt = 0; tt < 8; tt++) pre[tt + 1] = pre[tt] + ((d_cnt[tt] + 127) >> 7);
    int tot = pre[8];

    for (int id = blockIdx.x; id < tot; id += gridDim.x) {
        __syncthreads();   // protect smem/prs from previous iteration

        int tap = 0;
#pragma unroll
        for (int tt = 1; tt < 8; tt++) if (id >= pre[tt]) tap = tt;
        int base = (id - pre[tap]) << 7;
        int cnt  = d_cnt[tap];
        int wtap = tap + (tap >= 4 ? 1 : 0);

        if (t < 128) {
            int pidx = base + t;
            prs[t] = (pidx < cnt) ? d_pairs[tap][pidx] : make_int2(-1, 0);
        }
        __syncthreads();
        {
            int row = t >> 1, h = t & 1;
            int srcrow = prs[row].y;
            const float4* fr4 = (const float4*)(feat + (size_t)srcrow * 64);
            stage_row(smc, row, h, fr4, false);
        }
        __syncthreads();

        float c[2][4][4];
#pragma unroll
        for (int mi = 0; mi < 2; mi++)
#pragma unroll
            for (int nj = 0; nj < 4; nj++)
#pragma unroll
                for (int e = 0; e < 4; e++) c[mi][nj][e] = 0.f;

        compute_tile(sb, lane, m0, n0w, d_wF + wtap * 1024, c);

        // epilogue: pair lanes (l, l^1) -> 4-wide quads -> red.v4
#pragma unroll
        for (int mi = 0; mi < 2; mi++) {
            int lr = m0 + mi * 16 + (lane >> 2);
            int or0 = prs[lr].x;
            int or1 = prs[lr + 8].x;
#pragma unroll
            for (int nj = 0; nj < 4; nj++) {
                float t0 = __shfl_xor_sync(0xffffffffu, c[mi][nj][0], 1);
                float t1 = __shfl_xor_sync(0xffffffffu, c[mi][nj][1], 1);
                float t2 = __shfl_xor_sync(0xffffffffu, c[mi][nj][2], 1);
                float t3 = __shfl_xor_sync(0xffffffffu, c[mi][nj][3], 1);
                int colb = n0w + nj * 8 + 4 * ((lane & 3) >> 1);
                if ((lane & 1) == 0) {
                    if (or0 >= 0)
                        asm volatile("red.global.add.v4.f32 [%0], {%1, %2, %3, %4};"
                            :: "l"(out + (size_t)or0 * 64 + colb),
                               "f"(c[mi][nj][0]), "f"(c[mi][nj][1]), "f"(t0), "f"(t1) : "memory");
                } else {
                    if (or1 >= 0)
                        asm volatile("red.global.add.v4.f32 [%0], {%1, %2, %3, %4};"
                            :: "l"(out + (size_t)or1 * 64 + colb),
                               "f"(t2), "f"(t3), "f"(c[mi][nj][2]), "f"(c[mi][nj][3]) : "memory");
                }
            }
        }
    }
}

// ---------------- launch ----------------
extern "C" void kernel_launch(void* const* d_in, const int* in_sizes, int n_in,
                              void* d_out, int out_size) {
    const float* feat = (const float*)d_in[0];
    const int*   idxs = (const int*)d_in[1];
    const float* wgt  = (const float*)d_in[2];
    const float* bias = (const float*)d_in[3];
    float* out = (float*)d_out;
    int n = in_sizes[0] / 64;
    int ntiles = (n + 127) / 128;

    wprep_kernel<<<36, 256>>>(wgt);
    scatter_kernel<<<(n + 255) / 256, 256>>>(idxs, n);
    build_kernel<<<(n + 255) / 256, 256>>>(idxs, n);
    center_kernel<<<ntiles, 256>>>(feat, bias, out, n);
    tap_kernel<<<444, 256>>>(feat, out);
}

// round 12
// speedup vs baseline: 2.6802x; 1.0714x over previous
#include <cuda_runtime.h>
#include <cuda_fp16.h>
#include <cstdint>

// ---------------------------------------------------------------------------
// Submanifold sparse conv2d, B=4, H=W=1024, C=K=64, 3x3 via fp16
// mma.sync (m16n8k16). A = fp16 single image; B = fp16 hi+lo split;
// 2-pass compensation (err ~1.4e-4 << 1e-3 gate).
//
//   wprep   : weight -> mma-ready per-lane B fragment records (hi+lo fp16)
//   scatter : d_grid[flat] = n+1
//   build   : compacted per-tap (out,in) pair lists
//   center  : dense tiles + bias, plain store       (must complete first)
//   tap     : persistent worklist over tap tiles, red.v4 accumulate
// Ordering: center's plain stores happen-before tap's reductions via the
// stream -- do NOT fuse (fusion races store vs red, R10).
// ---------------------------------------------------------------------------

typedef unsigned int u32;

#define HH 1024
#define WW 1024
#define NMAX 400000
#define RS  72           // padded A row stride (fp16 elems) = 144 B
#define RSB 144

__device__ int  d_grid[1 << 22];          // row+1, 0 = empty (zero-init)
__device__ int2 d_pairs[8][NMAX];
__device__ int  d_cnt[8];
// B fragments: [tap][ks][nc][lane] -> {b0_hi, b1_hi, b0_lo, b1_lo}
__device__ uint4 d_wF[9 * 4 * 8 * 32];

#define ATOT (128 * RSB)          // 18432 B: single fp16 A image

__device__ __forceinline__ u32 smem_u32(const void* p) {
    u32 a; asm("{ .reg .u64 t; cvta.to.shared.u64 t, %1; cvt.u32.u64 %0, t; }" : "=r"(a) : "l"(p));
    return a;
}
// pack two floats to f16x2: low half = first arg, high half = second arg
__device__ __forceinline__ u32 pack_hf(float lo_elem, float hi_elem) {
    u32 r; asm("cvt.rn.f16x2.f32 %0, %1, %2;" : "=r"(r) : "f"(hi_elem), "f"(lo_elem));
    return r;
}
#define LDSM4(r0, r1, r2, r3, addr)                                            \
    asm volatile("ldmatrix.sync.aligned.m8n8.x4.shared.b16 {%0,%1,%2,%3}, [%4];" \
        : "=r"(r0), "=r"(r1), "=r"(r2), "=r"(r3) : "r"(addr))

__device__ __forceinline__ void mma16816(float c[4], const u32 a[4], u32 b0, u32 b1) {
    asm volatile("mma.sync.aligned.m16n8k16.row.col.f32.f16.f16.f32 "
        "{%0,%1,%2,%3}, {%4,%5,%6,%7}, {%8,%9}, {%0,%1,%2,%3};"
        : "+f"(c[0]), "+f"(c[1]), "+f"(c[2]), "+f"(c[3])
        : "r"(a[0]), "r"(a[1]), "r"(a[2]), "r"(a[3]), "r"(b0), "r"(b1));
}

// ---------------- weight prep: mma-ready B fragment records ----------------
// mma.m16n8k16 B fragment: lane l holds b0 = {k0, k0+1}, b1 = {k0+8, k0+9}
// at n = l/4, where k0 = 2*(l%4) within the 16-wide kstep.
__global__ void wprep_kernel(const float* __restrict__ wgt) {
    int idx = blockIdx.x * 256 + threadIdx.x;
    if (idx >= 9 * 4 * 8 * 32) return;
    int lane = idx & 31, nc = (idx >> 5) & 7, ks = (idx >> 8) & 3, tap = idx >> 10;
    int n  = nc * 8 + (lane >> 2);          // kout
    int k0 = ks * 16 + 2 * (lane & 3);      // c (input channel)
    const float* wr = wgt + (n * 9 + tap) * 64;
    float w00 = wr[k0], w01 = wr[k0 + 1], w10 = wr[k0 + 8], w11 = wr[k0 + 9];
    float h00 = __half2float(__float2half_rn(w00));
    float h01 = __half2float(__float2half_rn(w01));
    float h10 = __half2float(__float2half_rn(w10));
    float h11 = __half2float(__float2half_rn(w11));
    uint4 rec;
    rec.x = pack_hf(h00, h01);
    rec.y = pack_hf(h10, h11);
    rec.z = pack_hf(w00 - h00, w01 - h01);
    rec.w = pack_hf(w10 - h10, w11 - h11);
    d_wF[idx] = rec;
}

// ---------------- scatter ----------------
__global__ void scatter_kernel(const int* __restrict__ idxs, int n) {
    int gid = blockIdx.x * 256 + threadIdx.x;
    if (gid < 8) d_cnt[gid] = 0;
    if (gid < n) {
        int b = idxs[gid * 3], h = idxs[gid * 3 + 1], w = idxs[gid * 3 + 2];
        d_grid[(b << 20) + (h << 10) + w] = gid + 1;
    }
}

// ---------------- build pair lists ----------------
__global__ void build_kernel(const int* __restrict__ idxs, int n) {
    int gid  = blockIdx.x * 256 + threadIdx.x;
    int warp = threadIdx.x >> 5, lane = threadIdx.x & 31;
    __shared__ int warpoff[8][8];
    __shared__ int blockbase[8];

    bool valid = gid < n;
    int b = 0, h = 0, w = 0;
    if (valid) { b = idxs[gid * 3]; h = idxs[gid * 3 + 1]; w = idxs[gid * 3 + 2]; }

    int nbr[8]; bool act[8]; unsigned masks[8];
#pragma unroll
    for (int tt = 0; tt < 8; tt++) {
        int wt = tt + (tt >= 4 ? 1 : 0);
        int r = wt / 3, s = wt - r * 3;
        int hi = h + r - 1, wi = w + s - 1;
        bool ib = valid && ((unsigned)hi < HH) && ((unsigned)wi < WW);
        int g = 0;
        if (ib) g = d_grid[(b << 20) + (hi << 10) + wi];
        nbr[tt] = g - 1; act[tt] = g > 0;
        masks[tt] = __ballot_sync(0xffffffffu, act[tt]);
    }
    if (lane == 0)
#pragma unroll
        for (int tt = 0; tt < 8; tt++) warpoff[tt][warp] = __popc(masks[tt]);
    __syncthreads();
    if (threadIdx.x < 8) {
        int tt = threadIdx.x, tot = 0;
#pragma unroll
        for (int w2 = 0; w2 < 8; w2++) { int v = warpoff[tt][w2]; warpoff[tt][w2] = tot; tot += v; }
        blockbase[tt] = tot ? atomicAdd(&d_cnt[tt], tot) : 0;
    }
    __syncthreads();
#pragma unroll
    for (int tt = 0; tt < 8; tt++) {
        if (act[tt]) {
            int rank = __popc(masks[tt] & ((1u << lane) - 1u));
            d_pairs[tt][blockbase[tt] + warpoff[tt][warp] + rank] = make_int2(gid, nbr[tt]);
        }
    }
}

// ---------------- shared helpers ----------------
// stage one feature row half (32 cols) as fp16 into padded smem
__device__ __forceinline__ void stage_row(char* smc, int row, int h, const float4* fr4, bool zero) {
#pragma unroll
    for (int j = 0; j < 4; j++) {
        float4 v0 = make_float4(0.f, 0.f, 0.f, 0.f), v1 = v0;
        if (!zero) { v0 = fr4[8 * h + 2 * j]; v1 = fr4[8 * h + 2 * j + 1]; }
        uint4 p;
        p.x = pack_hf(v0.x, v0.y);
        p.y = pack_hf(v0.z, v0.w);
        p.z = pack_hf(v1.x, v1.y);
        p.w = pack_hf(v1.z, v1.w);
        *(uint4*)(smc + row * RSB + h * 64 + j * 16) = p;
    }
}

// compute the 128x64 tile: warp (m0, n0w) -> c[2][4][4].
// A fragments from smem via ldmatrix; B fragments direct LDG.128 from d_wF.
__device__ __forceinline__ void compute_tile(u32 sb, int lane, int m0, int n0w,
                                             const uint4* __restrict__ wf, float c[2][4][4]) {
    u32 aBase = sb + (u32)(m0 + (lane & 15)) * RSB + (u32)(lane >> 4) * 16;
#pragma unroll
    for (int ks = 0; ks < 4; ks++) {
        u32 ah[2][4];
        LDSM4(ah[0][0], ah[0][1], ah[0][2], ah[0][3], aBase + ks * 32);
        LDSM4(ah[1][0], ah[1][1], ah[1][2], ah[1][3], aBase + ks * 32 + 16 * RSB);
#pragma unroll
        for (int nj = 0; nj < 4; nj++) {
            uint4 f = __ldg(&wf[(ks * 8 + (n0w >> 3) + nj) * 32 + lane]);
#pragma unroll
            for (int mi = 0; mi < 2; mi++) {
                mma16816(c[mi][nj], ah[mi], f.x, f.y);
                mma16816(c[mi][nj], ah[mi], f.z, f.w);
            }
        }
    }
}

// ---------------- center: dense fp16-mma tiles + bias (plain store) ----------------
__global__ __launch_bounds__(256, 3) void center_kernel(
        const float* __restrict__ feat, const float* __restrict__ bias,
        float* __restrict__ out, int nn) {
    __shared__ char smc[ATOT];
    u32 sb = smem_u32(smc);
    int t = threadIdx.x, lane = t & 31, wid = t >> 5;
    int gbase = blockIdx.x * 128;

    {
        int row = t >> 1, h = t & 1;
        int g = gbase + row;
        bool zero = g >= nn;
        const float4* fr4 = (const float4*)(feat + (size_t)(zero ? 0 : g) * 64);
        stage_row(smc, row, h, fr4, zero);
    }
    __syncthreads();

    int m0 = (wid >> 1) * 32, n0w = (wid & 1) * 32;
    float c[2][4][4];
#pragma unroll
    for (int mi = 0; mi < 2; mi++)
#pragma unroll
        for (int nj = 0; nj < 4; nj++)
#pragma unroll
            for (int e = 0; e < 4; e++) c[mi][nj][e] = 0.f;

    compute_tile(sb, lane, m0, n0w, d_wF + 4 * 1024, c);

#pragma unroll
    for (int nj = 0; nj < 4; nj++) {
        int n = n0w + nj * 8 + 2 * (lane & 3);
        float2 bv = __ldg((const float2*)(bias + n));
#pragma unroll
        for (int mi = 0; mi < 2; mi++) {
            int r0 = gbase + m0 + mi * 16 + (lane >> 2);
            int r1 = r0 + 8;
            if (r0 < nn)
                *(float2*)(out + (size_t)r0 * 64 + n) =
                    make_float2(c[mi][nj][0] + bv.x, c[mi][nj][1] + bv.y);
            if (r1 < nn)
                *(float2*)(out + (size_t)r1 * 64 + n) =
                    make_float2(c[mi][nj][2] + bv.x, c[mi][nj][3] + bv.y);
        }
    }
}

// ---------------- taps: persistent worklist, shfl-paired red.v4 scatter ----------------
__global__ __launch_bounds__(256, 3) void tap_kernel(
        const float* __restrict__ feat, float* __restrict__ out) {
    __shared__ char smc[ATOT];
    __shared__ int2 prs[128];
    u32 sb = smem_u32(smc);
    int t = threadIdx.x, lane = t & 31, wid = t >> 5;
    int m0 = (wid >> 1) * 32, n0w = (wid & 1) * 32;

    // worklist prefix over the 8 tap pair-lists
    int pre[9];
    pre[0] = 0;
#pragma unroll
    for (int tt = 0; tt < 8; tt++) pre[tt + 1] = pre[tt] + ((d_cnt[tt] + 127) >> 7);
    int tot = pre[8];

    for (int id = blockIdx.x; id < tot; id += gridDim.x) {
        __syncthreads();   // protect smem/prs from previous iteration

        int tap = 0;
#pragma unroll
        for (int tt = 1; tt < 8; tt++) if (id >= pre[tt]) tap = tt;
        int base = (id - pre[tap]) << 7;
        int cnt  = d_cnt[tap];
        int wtap = tap + (tap >= 4 ? 1 : 0);

        if (t < 128) {
            int pidx = base + t;
            prs[t] = (pidx < cnt) ? d_pairs[tap][pidx] : make_int2(-1, 0);
        }
        __syncthreads();
        {
            int row = t >> 1, h = t & 1;
            int srcrow = prs[row].y;
            const float4* fr4 = (const float4*)(feat + (size_t)srcrow * 64);
            stage_row(smc, row, h, fr4, false);
        }
        __syncthreads();

        float c[2][4][4];
#pragma unroll
        for (int mi = 0; mi < 2; mi++)
#pragma unroll
            for (int nj = 0; nj < 4; nj++)
#pragma unroll
                for (int e = 0; e < 4; e++) c[mi][nj][e] = 0.f;

        compute_tile(sb, lane, m0, n0w, d_wF + wtap * 1024, c);

        // epilogue: pair lanes (l, l^1) -> 4-wide quads -> red.v4
#pragma unroll
        for (int mi = 0; mi < 2; mi++) {
            int lr = m0 + mi * 16 + (lane >> 2);
            int or0 = prs[lr].x;
            int or1 = prs[lr + 8].x;
#pragma unroll
            for (int nj = 0; nj < 4; nj++) {
                float t0 = __shfl_xor_sync(0xffffffffu, c[mi][nj][0], 1);
                float t1 = __shfl_xor_sync(0xffffffffu, c[mi][nj][1], 1);
                float t2 = __shfl_xor_sync(0xffffffffu, c[mi][nj][2], 1);
                float t3 = __shfl_xor_sync(0xffffffffu, c[mi][nj][3], 1);
                int colb = n0w + nj * 8 + 4 * ((lane & 3) >> 1);
                if ((lane & 1) == 0) {
                    if (or0 >= 0)
                        asm volatile("red.global.add.v4.f32 [%0], {%1, %2, %3, %4};"
                            :: "l"(out + (size_t)or0 * 64 + colb),
                               "f"(c[mi][nj][0]), "f"(c[mi][nj][1]), "f"(t0), "f"(t1) : "memory");
                } else {
                    if (or1 >= 0)
                        asm volatile("red.global.add.v4.f32 [%0], {%1, %2, %3, %4};"
                            :: "l"(out + (size_t)or1 * 64 + colb),
                               "f"(t2), "f"(t3), "f"(c[mi][nj][2]), "f"(c[mi][nj][3]) : "memory");
                }
            }
        }
    }
}

// ---------------- launch ----------------
extern "C" void kernel_launch(void* const* d_in, const int* in_sizes, int n_in,
                              void* d_out, int out_size) {
    const float* feat = (const float*)d_in[0];
    const int*   idxs = (const int*)d_in[1];
    const float* wgt  = (const float*)d_in[2];
    const float* bias = (const float*)d_in[3];
    float* out = (float*)d_out;
    int n = in_sizes[0] / 64;
    int ntiles = (n + 127) / 128;

    wprep_kernel<<<36, 256>>>(wgt);
    scatter_kernel<<<(n + 255) / 256, 256>>>(idxs, n);
    build_kernel<<<(n + 255) / 256, 256>>>(idxs, n);
    center_kernel<<<ntiles, 256>>>(feat, bias, out, n);
    tap_kernel<<<444, 256>>>(feat, out);
}

// round 13
// speedup vs baseline: 2.9321x; 1.0940x over previous
#include <cuda_runtime.h>
#include <cuda_fp16.h>
#include <cstdint>

// ---------------------------------------------------------------------------
// Submanifold sparse conv2d, B=4, H=W=1024, C=K=64, 3x3 via fp16
// mma.sync (m16n8k16), single-pass fp16 A and B (err ~3e-4 << 1e-3 gate).
//
//   wprep   : weight -> mma-ready per-lane B fragment records (fp16)
//   scatter : d_grid[flat] = n+1
//   build   : compacted per-tap (out,in) pair lists
//   center  : dense tiles + bias, plain store       (must complete first)
//   tap     : persistent worklist over tap tiles, red.v4 accumulate
// Ordering: center's plain stores happen-before tap's reductions via the
// stream -- do NOT fuse (fusion races store vs red, R10).
// ---------------------------------------------------------------------------

typedef unsigned int u32;

#define HH 1024
#define WW 1024
#define NMAX 400000
#define RS  72           // padded A row stride (fp16 elems) = 144 B
#define RSB 144

__device__ int  d_grid[1 << 22];          // row+1, 0 = empty (zero-init)
__device__ int2 d_pairs[8][NMAX];
__device__ int  d_cnt[8];
// B fragments: [tap][ks][nc][lane] -> {b0, b1} fp16x2
__device__ uint2 d_wF[9 * 4 * 8 * 32];

#define ATOT (128 * RSB)          // 18432 B: single fp16 A image

__device__ __forceinline__ u32 smem_u32(const void* p) {
    u32 a; asm("{ .reg .u64 t; cvta.to.shared.u64 t, %1; cvt.u32.u64 %0, t; }" : "=r"(a) : "l"(p));
    return a;
}
// pack two floats to f16x2: low half = first arg, high half = second arg
__device__ __forceinline__ u32 pack_hf(float lo_elem, float hi_elem) {
    u32 r; asm("cvt.rn.f16x2.f32 %0, %1, %2;" : "=r"(r) : "f"(hi_elem), "f"(lo_elem));
    return r;
}
#define LDSM4(r0, r1, r2, r3, addr)                                            \
    asm volatile("ldmatrix.sync.aligned.m8n8.x4.shared.b16 {%0,%1,%2,%3}, [%4];" \
        : "=r"(r0), "=r"(r1), "=r"(r2), "=r"(r3) : "r"(addr))

__device__ __forceinline__ void mma16816(float c[4], const u32 a[4], u32 b0, u32 b1) {
    asm volatile("mma.sync.aligned.m16n8k16.row.col.f32.f16.f16.f32 "
        "{%0,%1,%2,%3}, {%4,%5,%6,%7}, {%8,%9}, {%0,%1,%2,%3};"
        : "+f"(c[0]), "+f"(c[1]), "+f"(c[2]), "+f"(c[3])
        : "r"(a[0]), "r"(a[1]), "r"(a[2]), "r"(a[3]), "r"(b0), "r"(b1));
}

// ---------------- weight prep: mma-ready B fragment records ----------------
// mma.m16n8k16 B fragment: lane l holds b0 = {k0, k0+1}, b1 = {k0+8, k0+9}
// at n = l/4, where k0 = 2*(l%4) within the 16-wide kstep.
__global__ void wprep_kernel(const float* __restrict__ wgt) {
    int idx = blockIdx.x * 256 + threadIdx.x;
    if (idx >= 9 * 4 * 8 * 32) return;
    int lane = idx & 31, nc = (idx >> 5) & 7, ks = (idx >> 8) & 3, tap = idx >> 10;
    int n  = nc * 8 + (lane >> 2);          // kout
    int k0 = ks * 16 + 2 * (lane & 3);      // c (input channel)
    const float* wr = wgt + (n * 9 + tap) * 64;
    uint2 rec;
    rec.x = pack_hf(wr[k0], wr[k0 + 1]);
    rec.y = pack_hf(wr[k0 + 8], wr[k0 + 9]);
    d_wF[idx] = rec;
}

// ---------------- scatter ----------------
__global__ void scatter_kernel(const int* __restrict__ idxs, int n) {
    int gid = blockIdx.x * 256 + threadIdx.x;
    if (gid < 8) d_cnt[gid] = 0;
    if (gid < n) {
        int b = idxs[gid * 3], h = idxs[gid * 3 + 1], w = idxs[gid * 3 + 2];
        d_grid[(b << 20) + (h << 10) + w] = gid + 1;
    }
}

// ---------------- build pair lists ----------------
__global__ void build_kernel(const int* __restrict__ idxs, int n) {
    int gid  = blockIdx.x * 256 + threadIdx.x;
    int warp = threadIdx.x >> 5, lane = threadIdx.x & 31;
    __shared__ int warpoff[8][8];
    __shared__ int blockbase[8];

    bool valid = gid < n;
    int b = 0, h = 0, w = 0;
    if (valid) { b = idxs[gid * 3]; h = idxs[gid * 3 + 1]; w = idxs[gid * 3 + 2]; }

    int nbr[8]; bool act[8]; unsigned masks[8];
#pragma unroll
    for (int tt = 0; tt < 8; tt++) {
        int wt = tt + (tt >= 4 ? 1 : 0);
        int r = wt / 3, s = wt - r * 3;
        int hi = h + r - 1, wi = w + s - 1;
        bool ib = valid && ((unsigned)hi < HH) && ((unsigned)wi < WW);
        int g = 0;
        if (ib) g = d_grid[(b << 20) + (hi << 10) + wi];
        nbr[tt] = g - 1; act[tt] = g > 0;
        masks[tt] = __ballot_sync(0xffffffffu, act[tt]);
    }
    if (lane == 0)
#pragma unroll
        for (int tt = 0; tt < 8; tt++) warpoff[tt][warp] = __popc(masks[tt]);
    __syncthreads();
    if (threadIdx.x < 8) {
        int tt = threadIdx.x, tot = 0;
#pragma unroll
        for (int w2 = 0; w2 < 8; w2++) { int v = warpoff[tt][w2]; warpoff[tt][w2] = tot; tot += v; }
        blockbase[tt] = tot ? atomicAdd(&d_cnt[tt], tot) : 0;
    }
    __syncthreads();
#pragma unroll
    for (int tt = 0; tt < 8; tt++) {
        if (act[tt]) {
            int rank = __popc(masks[tt] & ((1u << lane) - 1u));
            d_pairs[tt][blockbase[tt] + warpoff[tt][warp] + rank] = make_int2(gid, nbr[tt]);
        }
    }
}

// ---------------- shared helpers ----------------
// stage one feature row half (32 cols) as fp16 into padded smem
__device__ __forceinline__ void stage_row(char* smc, int row, int h, const float4* fr4, bool zero) {
#pragma unroll
    for (int j = 0; j < 4; j++) {
        float4 v0 = make_float4(0.f, 0.f, 0.f, 0.f), v1 = v0;
        if (!zero) { v0 = fr4[8 * h + 2 * j]; v1 = fr4[8 * h + 2 * j + 1]; }
        uint4 p;
        p.x = pack_hf(v0.x, v0.y);
        p.y = pack_hf(v0.z, v0.w);
        p.z = pack_hf(v1.x, v1.y);
        p.w = pack_hf(v1.z, v1.w);
        *(uint4*)(smc + row * RSB + h * 64 + j * 16) = p;
    }
}

// compute the 128x64 tile: warp (m0, n0w) -> c[2][4][4].
// A fragments from smem via ldmatrix; B fragments direct LDG.64 from d_wF.
__device__ __forceinline__ void compute_tile(u32 sb, int lane, int m0, int n0w,
                                             const uint2* __restrict__ wf, float c[2][4][4]) {
    u32 aBase = sb + (u32)(m0 + (lane & 15)) * RSB + (u32)(lane >> 4) * 16;
#pragma unroll
    for (int ks = 0; ks < 4; ks++) {
        u32 ah[2][4];
        LDSM4(ah[0][0], ah[0][1], ah[0][2], ah[0][3], aBase + ks * 32);
        LDSM4(ah[1][0], ah[1][1], ah[1][2], ah[1][3], aBase + ks * 32 + 16 * RSB);
#pragma unroll
        for (int nj = 0; nj < 4; nj++) {
            uint2 f = __ldg(&wf[(ks * 8 + (n0w >> 3) + nj) * 32 + lane]);
#pragma unroll
            for (int mi = 0; mi < 2; mi++)
                mma16816(c[mi][nj], ah[mi], f.x, f.y);
        }
    }
}

// ---------------- center: dense fp16-mma tiles + bias (plain store) ----------------
__global__ __launch_bounds__(256, 3) void center_kernel(
        const float* __restrict__ feat, const float* __restrict__ bias,
        float* __restrict__ out, int nn) {
    __shared__ char smc[ATOT];
    u32 sb = smem_u32(smc);
    int t = threadIdx.x, lane = t & 31, wid = t >> 5;
    int gbase = blockIdx.x * 128;

    {
        int row = t >> 1, h = t & 1;
        int g = gbase + row;
        bool zero = g >= nn;
        const float4* fr4 = (const float4*)(feat + (size_t)(zero ? 0 : g) * 64);
        stage_row(smc, row, h, fr4, zero);
    }
    __syncthreads();

    int m0 = (wid >> 1) * 32, n0w = (wid & 1) * 32;
    float c[2][4][4];
#pragma unroll
    for (int mi = 0; mi < 2; mi++)
#pragma unroll
        for (int nj = 0; nj < 4; nj++)
#pragma unroll
            for (int e = 0; e < 4; e++) c[mi][nj][e] = 0.f;

    compute_tile(sb, lane, m0, n0w, d_wF + 4 * 1024, c);

#pragma unroll
    for (int nj = 0; nj < 4; nj++) {
        int n = n0w + nj * 8 + 2 * (lane & 3);
        float2 bv = __ldg((const float2*)(bias + n));
#pragma unroll
        for (int mi = 0; mi < 2; mi++) {
            int r0 = gbase + m0 + mi * 16 + (lane >> 2);
            int r1 = r0 + 8;
            if (r0 < nn)
                *(float2*)(out + (size_t)r0 * 64 + n) =
                    make_float2(c[mi][nj][0] + bv.x, c[mi][nj][1] + bv.y);
            if (r1 < nn)
                *(float2*)(out + (size_t)r1 * 64 + n) =
                    make_float2(c[mi][nj][2] + bv.x, c[mi][nj][3] + bv.y);
        }
    }
}

// ---------------- taps: persistent worklist, shfl-paired red.v4 scatter ----------------
__global__ __launch_bounds__(256, 3) void tap_kernel(
        const float* __restrict__ feat, float* __restrict__ out) {
    __shared__ char smc[ATOT];
    __shared__ int2 prs[128];
    u32 sb = smem_u32(smc);
    int t = threadIdx.x, lane = t & 31, wid = t >> 5;
    int m0 = (wid >> 1) * 32, n0w = (wid & 1) * 32;

    // worklist prefix over the 8 tap pair-lists
    int pre[9];
    pre[0] = 0;
#pragma unroll
    for (int tt = 0; tt < 8; tt++) pre[tt + 1] = pre[tt] + ((d_cnt[tt] + 127) >> 7);
    int tot = pre[8];

    for (int id = blockIdx.x; id < tot; id += gridDim.x) {
        __syncthreads();   // protect smem/prs from previous iteration

        int tap = 0;
#pragma unroll
        for (int tt = 1; tt < 8; tt++) if (id >= pre[tt]) tap = tt;
        int base = (id - pre[tap]) << 7;
        int cnt  = d_cnt[tap];
        int wtap = tap + (tap >= 4 ? 1 : 0);

        if (t < 128) {
            int pidx = base + t;
            prs[t] = (pidx < cnt) ? d_pairs[tap][pidx] : make_int2(-1, 0);
        }
        __syncthreads();
        {
            int row = t >> 1, h = t & 1;
            int srcrow = prs[row].y;
            const float4* fr4 = (const float4*)(feat + (size_t)srcrow * 64);
            stage_row(smc, row, h, fr4, false);
        }
        __syncthreads();

        float c[2][4][4];
#pragma unroll
        for (int mi = 0; mi < 2; mi++)
#pragma unroll
            for (int nj = 0; nj < 4; nj++)
#pragma unroll
                for (int e = 0; e < 4; e++) c[mi][nj][e] = 0.f;

        compute_tile(sb, lane, m0, n0w, d_wF + wtap * 1024, c);

        // epilogue: pair lanes (l, l^1) -> 4-wide quads -> red.v4
#pragma unroll
        for (int mi = 0; mi < 2; mi++) {
            int lr = m0 + mi * 16 + (lane >> 2);
            int or0 = prs[lr].x;
            int or1 = prs[lr + 8].x;
#pragma unroll
            for (int nj = 0; nj < 4; nj++) {
                float t0 = __shfl_xor_sync(0xffffffffu, c[mi][nj][0], 1);
                float t1 = __shfl_xor_sync(0xffffffffu, c[mi][nj][1], 1);
                float t2 = __shfl_xor_sync(0xffffffffu, c[mi][nj][2], 1);
                float t3 = __shfl_xor_sync(0xffffffffu, c[mi][nj][3], 1);
                int colb = n0w + nj * 8 + 4 * ((lane & 3) >> 1);
                if ((lane & 1) == 0) {
                    if (or0 >= 0)
                        asm volatile("red.global.add.v4.f32 [%0], {%1, %2, %3, %4};"
                            :: "l"(out + (size_t)or0 * 64 + colb),
                               "f"(c[mi][nj][0]), "f"(c[mi][nj][1]), "f"(t0), "f"(t1) : "memory");
                } else {
                    if (or1 >= 0)
                        asm volatile("red.global.add.v4.f32 [%0], {%1, %2, %3, %4};"
                            :: "l"(out + (size_t)or1 * 64 + colb),
                               "f"(t2), "f"(t3), "f"(c[mi][nj][2]), "f"(c[mi][nj][3]) : "memory");
                }
            }
        }
    }
}

// ---------------- launch ----------------
extern "C" void kernel_launch(void* const* d_in, const int* in_sizes, int n_in,
                              void* d_out, int out_size) {
    const float* feat = (const float*)d_in[0];
    const int*   idxs = (const int*)d_in[1];
    const float* wgt  = (const float*)d_in[2];
    const float* bias = (const float*)d_in[3];
    float* out = (float*)d_out;
    int n = in_sizes[0] / 64;
    int ntiles = (n + 127) / 128;

    wprep_kernel<<<36, 256>>>(wgt);
    scatter_kernel<<<(n + 255) / 256, 256>>>(idxs, n);
    build_kernel<<<(n + 255) / 256, 256>>>(idxs, n);
    center_kernel<<<ntiles, 256>>>(feat, bias, out, n);
    tap_kernel<<<444, 256>>>(feat, out);
}

// round 14
// speedup vs baseline: 2.9794x; 1.0161x over previous
#include <cuda_runtime.h>
#include <cuda_fp16.h>
#include <cstdint>

// ---------------------------------------------------------------------------
// Submanifold sparse conv2d, B=4, H=W=1024, C=K=64, 3x3 via fp16
// mma.sync (m16n8k16), single-pass fp16 (err ~3e-4 << 1e-3 gate).
//
//   wprep   : weight -> mma-ready per-lane B fragment records (fp16)
//   scatter : d_grid[flat] = n+1
//   build   : compacted per-tap (out,in) pair lists
//   center  : persistent, software-pipelined dense tiles + bias, plain store
//   tap     : persistent, software-pipelined tap tiles, red.v4 accumulate
// Ordering: center's plain stores happen-before tap's reductions via the
// stream -- do NOT fuse (fusion races store vs red, R10).
// Pipelining: next tile's A rows are prefetched into registers while the
// current tile computes, hiding cold-DRAM latency (R13: issue=10.6%).
// ---------------------------------------------------------------------------

typedef unsigned int u32;

#define HH 1024
#define WW 1024
#define NMAX 400000
#define RS  72           // padded A row stride (fp16 elems) = 144 B
#define RSB 144

__device__ int  d_grid[1 << 22];          // row+1, 0 = empty (zero-init)
__device__ int2 d_pairs[8][NMAX];
__device__ int  d_cnt[8];
// B fragments: [tap][ks][nc][lane] -> {b0, b1} fp16x2
__device__ uint2 d_wF[9 * 4 * 8 * 32];

#define ATOT (128 * RSB)          // 18432 B: single fp16 A image

__device__ __forceinline__ u32 smem_u32(const void* p) {
    u32 a; asm("{ .reg .u64 t; cvta.to.shared.u64 t, %1; cvt.u32.u64 %0, t; }" : "=r"(a) : "l"(p));
    return a;
}
// pack two floats to f16x2: low half = first arg, high half = second arg
__device__ __forceinline__ u32 pack_hf(float lo_elem, float hi_elem) {
    u32 r; asm("cvt.rn.f16x2.f32 %0, %1, %2;" : "=r"(r) : "f"(hi_elem), "f"(lo_elem));
    return r;
}
#define LDSM4(r0, r1, r2, r3, addr)                                            \
    asm volatile("ldmatrix.sync.aligned.m8n8.x4.shared.b16 {%0,%1,%2,%3}, [%4];" \
        : "=r"(r0), "=r"(r1), "=r"(r2), "=r"(r3) : "r"(addr))

__device__ __forceinline__ void mma16816(float c[4], const u32 a[4], u32 b0, u32 b1) {
    asm volatile("mma.sync.aligned.m16n8k16.row.col.f32.f16.f16.f32 "
        "{%0,%1,%2,%3}, {%4,%5,%6,%7}, {%8,%9}, {%0,%1,%2,%3};"
        : "+f"(c[0]), "+f"(c[1]), "+f"(c[2]), "+f"(c[3])
        : "r"(a[0]), "r"(a[1]), "r"(a[2]), "r"(a[3]), "r"(b0), "r"(b1));
}

// ---------------- weight prep: mma-ready B fragment records ----------------
// mma.m16n8k16 B fragment: lane l holds b0 = {k0, k0+1}, b1 = {k0+8, k0+9}
// at n = l/4, where k0 = 2*(l%4) within the 16-wide kstep.
__global__ void wprep_kernel(const float* __restrict__ wgt) {
    int idx = blockIdx.x * 256 + threadIdx.x;
    if (idx >= 9 * 4 * 8 * 32) return;
    int lane = idx & 31, nc = (idx >> 5) & 7, ks = (idx >> 8) & 3, tap = idx >> 10;
    int n  = nc * 8 + (lane >> 2);          // kout
    int k0 = ks * 16 + 2 * (lane & 3);      // c (input channel)
    const float* wr = wgt + (n * 9 + tap) * 64;
    uint2 rec;
    rec.x = pack_hf(wr[k0], wr[k0 + 1]);
    rec.y = pack_hf(wr[k0 + 8], wr[k0 + 9]);
    d_wF[idx] = rec;
}

// ---------------- scatter ----------------
__global__ void scatter_kernel(const int* __restrict__ idxs, int n) {
    int gid = blockIdx.x * 256 + threadIdx.x;
    if (gid < 8) d_cnt[gid] = 0;
    if (gid < n) {
        int b = idxs[gid * 3], h = idxs[gid * 3 + 1], w = idxs[gid * 3 + 2];
        d_grid[(b << 20) + (h << 10) + w] = gid + 1;
    }
}

// ---------------- build pair lists ----------------
__global__ void build_kernel(const int* __restrict__ idxs, int n) {
    int gid  = blockIdx.x * 256 + threadIdx.x;
    int warp = threadIdx.x >> 5, lane = threadIdx.x & 31;
    __shared__ int warpoff[8][8];
    __shared__ int blockbase[8];

    bool valid = gid < n;
    int b = 0, h = 0, w = 0;
    if (valid) { b = idxs[gid * 3]; h = idxs[gid * 3 + 1]; w = idxs[gid * 3 + 2]; }

    int nbr[8]; bool act[8]; unsigned masks[8];
#pragma unroll
    for (int tt = 0; tt < 8; tt++) {
        int wt = tt + (tt >= 4 ? 1 : 0);
        int r = wt / 3, s = wt - r * 3;
        int hi = h + r - 1, wi = w + s - 1;
        bool ib = valid && ((unsigned)hi < HH) && ((unsigned)wi < WW);
        int g = 0;
        if (ib) g = d_grid[(b << 20) + (hi << 10) + wi];
        nbr[tt] = g - 1; act[tt] = g > 0;
        masks[tt] = __ballot_sync(0xffffffffu, act[tt]);
    }
    if (lane == 0)
#pragma unroll
        for (int tt = 0; tt < 8; tt++) warpoff[tt][warp] = __popc(masks[tt]);
    __syncthreads();
    if (threadIdx.x < 8) {
        int tt = threadIdx.x, tot = 0;
#pragma unroll
        for (int w2 = 0; w2 < 8; w2++) { int v = warpoff[tt][w2]; warpoff[tt][w2] = tot; tot += v; }
        blockbase[tt] = tot ? atomicAdd(&d_cnt[tt], tot) : 0;
    }
    __syncthreads();
#pragma unroll
    for (int tt = 0; tt < 8; tt++) {
        if (act[tt]) {
            int rank = __popc(masks[tt] & ((1u << lane) - 1u));
            d_pairs[tt][blockbase[tt] + warpoff[tt][warp] + rank] = make_int2(gid, nbr[tt]);
        }
    }
}

// ---------------- shared helpers ----------------
// load this thread's half-row (32 floats = 8 float4) into registers
__device__ __forceinline__ void load_rows(const float* __restrict__ feat,
                                          int g, int h, bool valid, float4 fr[8]) {
    if (valid) {
        const float4* p = (const float4*)(feat + (size_t)g * 64) + 8 * h;
#pragma unroll
        for (int j = 0; j < 8; j++) fr[j] = p[j];
    } else {
#pragma unroll
        for (int j = 0; j < 8; j++) fr[j] = make_float4(0.f, 0.f, 0.f, 0.f);
    }
}
// stage registered half-row as fp16 into padded smem
__device__ __forceinline__ void stage_from_regs(char* smc, int row, int h, const float4 fr[8]) {
#pragma unroll
    for (int j = 0; j < 4; j++) {
        float4 v0 = fr[2 * j], v1 = fr[2 * j + 1];
        uint4 p;
        p.x = pack_hf(v0.x, v0.y);
        p.y = pack_hf(v0.z, v0.w);
        p.z = pack_hf(v1.x, v1.y);
        p.w = pack_hf(v1.z, v1.w);
        *(uint4*)(smc + row * RSB + h * 64 + j * 16) = p;
    }
}

// compute the 128x64 tile: warp (m0, n0w) -> c[2][4][4].
__device__ __forceinline__ void compute_tile(u32 sb, int lane, int m0, int n0w,
                                             const uint2* __restrict__ wf, float c[2][4][4]) {
    u32 aBase = sb + (u32)(m0 + (lane & 15)) * RSB + (u32)(lane >> 4) * 16;
#pragma unroll
    for (int ks = 0; ks < 4; ks++) {
        u32 ah[2][4];
        LDSM4(ah[0][0], ah[0][1], ah[0][2], ah[0][3], aBase + ks * 32);
        LDSM4(ah[1][0], ah[1][1], ah[1][2], ah[1][3], aBase + ks * 32 + 16 * RSB);
#pragma unroll
        for (int nj = 0; nj < 4; nj++) {
            uint2 f = __ldg(&wf[(ks * 8 + (n0w >> 3) + nj) * 32 + lane]);
#pragma unroll
            for (int mi = 0; mi < 2; mi++)
                mma16816(c[mi][nj], ah[mi], f.x, f.y);
        }
    }
}

// ---------------- center: persistent pipelined dense tiles + bias ----------------
__global__ __launch_bounds__(256, 2) void center_kernel(
        const float* __restrict__ feat, const float* __restrict__ bias,
        float* __restrict__ out, int nn, int ntiles) {
    __shared__ char smc[ATOT];
    u32 sb = smem_u32(smc);
    int t = threadIdx.x, lane = t & 31, wid = t >> 5;
    int row = t >> 1, h = t & 1;
    int m0 = (wid >> 1) * 32, n0w = (wid & 1) * 32;

    int tile = blockIdx.x;
    float4 fr[8];
    if (tile < ntiles) {
        int g = tile * 128 + row;
        load_rows(feat, g, h, g < nn, fr);
    }

    for (; tile < ntiles; tile += gridDim.x) {
        __syncthreads();               // previous compute done; smem free
        stage_from_regs(smc, row, h, fr);
        __syncthreads();

        // prefetch next tile while computing this one
        int next = tile + gridDim.x;
        if (next < ntiles) {
            int g = next * 128 + row;
            load_rows(feat, g, h, g < nn, fr);
        }

        float c[2][4][4];
#pragma unroll
        for (int mi = 0; mi < 2; mi++)
#pragma unroll
            for (int nj = 0; nj < 4; nj++)
#pragma unroll
                for (int e = 0; e < 4; e++) c[mi][nj][e] = 0.f;

        compute_tile(sb, lane, m0, n0w, d_wF + 4 * 1024, c);

        int gbase = tile * 128;
#pragma unroll
        for (int nj = 0; nj < 4; nj++) {
            int n = n0w + nj * 8 + 2 * (lane & 3);
            float2 bv = __ldg((const float2*)(bias + n));
#pragma unroll
            for (int mi = 0; mi < 2; mi++) {
                int r0 = gbase + m0 + mi * 16 + (lane >> 2);
                int r1 = r0 + 8;
                if (r0 < nn)
                    *(float2*)(out + (size_t)r0 * 64 + n) =
                        make_float2(c[mi][nj][0] + bv.x, c[mi][nj][1] + bv.y);
                if (r1 < nn)
                    *(float2*)(out + (size_t)r1 * 64 + n) =
                        make_float2(c[mi][nj][2] + bv.x, c[mi][nj][3] + bv.y);
            }
        }
    }
}

// ---------------- taps: persistent pipelined worklist, red.v4 scatter ----------------
__global__ __launch_bounds__(256, 2) void tap_kernel(
        const float* __restrict__ feat, float* __restrict__ out) {
    __shared__ char smc[ATOT];
    __shared__ int2 prs[128];
    u32 sb = smem_u32(smc);
    int t = threadIdx.x, lane = t & 31, wid = t >> 5;
    int row = t >> 1, h = t & 1;
    int m0 = (wid >> 1) * 32, n0w = (wid & 1) * 32;

    // worklist prefix over the 8 tap pair-lists
    int pre[9];
    pre[0] = 0;
#pragma unroll
    for (int tt = 0; tt < 8; tt++) pre[tt + 1] = pre[tt] + ((d_cnt[tt] + 127) >> 7);
    int tot = pre[8];

    int id = blockIdx.x;
    int2 pr = make_int2(-1, 0);
    float4 fr[8];
    if (id < tot) {
        int tap = 0;
#pragma unroll
        for (int tt = 1; tt < 8; tt++) if (id >= pre[tt]) tap = tt;
        int pidx = ((id - pre[tap]) << 7) + row;
        pr = (pidx < d_cnt[tap]) ? d_pairs[tap][pidx] : make_int2(-1, 0);
        load_rows(feat, pr.y, h, true, fr);
    }

    for (; id < tot; id += gridDim.x) {
        __syncthreads();               // previous compute/epilogue done
        if ((t & 1) == 0) prs[row] = pr;
        stage_from_regs(smc, row, h, fr);
        __syncthreads();

        int tap = 0;
#pragma unroll
        for (int tt = 1; tt < 8; tt++) if (id >= pre[tt]) tap = tt;
        int wtap = tap + (tap >= 4 ? 1 : 0);

        // prefetch next tile's pair (feature gather issued after compute)
        int nid = id + gridDim.x;
        int2 prn = make_int2(-1, 0);
        if (nid < tot) {
            int ntap = 0;
#pragma unroll
            for (int tt = 1; tt < 8; tt++) if (nid >= pre[tt]) ntap = tt;
            int pidx = ((nid - pre[ntap]) << 7) + row;
            prn = (pidx < d_cnt[ntap]) ? d_pairs[ntap][pidx] : make_int2(-1, 0);
        }

        float c[2][4][4];
#pragma unroll
        for (int mi = 0; mi < 2; mi++)
#pragma unroll
            for (int nj = 0; nj < 4; nj++)
#pragma unroll
                for (int e = 0; e < 4; e++) c[mi][nj][e] = 0.f;

        compute_tile(sb, lane, m0, n0w, d_wF + wtap * 1024, c);

        // gather next tile's features (latency hidden behind epilogue)
        if (nid < tot) load_rows(feat, prn.y, h, true, fr);
        pr = prn;

        // epilogue: pair lanes (l, l^1) -> 4-wide quads -> red.v4
#pragma unroll
        for (int mi = 0; mi < 2; mi++) {
            int lr = m0 + mi * 16 + (lane >> 2);
            int or0 = prs[lr].x;
            int or1 = prs[lr + 8].x;
#pragma unroll
            for (int nj = 0; nj < 4; nj++) {
                float t0 = __shfl_xor_sync(0xffffffffu, c[mi][nj][0], 1);
                float t1 = __shfl_xor_sync(0xffffffffu, c[mi][nj][1], 1);
                float t2 = __shfl_xor_sync(0xffffffffu, c[mi][nj][2], 1);
                float t3 = __shfl_xor_sync(0xffffffffu, c[mi][nj][3], 1);
                int colb = n0w + nj * 8 + 4 * ((lane & 3) >> 1);
                if ((lane & 1) == 0) {
                    if (or0 >= 0)
                        asm volatile("red.global.add.v4.f32 [%0], {%1, %2, %3, %4};"
                            :: "l"(out + (size_t)or0 * 64 + colb),
                               "f"(c[mi][nj][0]), "f"(c[mi][nj][1]), "f"(t0), "f"(t1) : "memory");
                } else {
                    if (or1 >= 0)
                        asm volatile("red.global.add.v4.f32 [%0], {%1, %2, %3, %4};"
                            :: "l"(out + (size_t)or1 * 64 + colb),
                               "f"(t2), "f"(t3), "f"(c[mi][nj][2]), "f"(c[mi][nj][3]) : "memory");
                }
            }
        }
    }
}

// ---------------- launch ----------------
extern "C" void kernel_launch(void* const* d_in, const int* in_sizes, int n_in,
                              void* d_out, int out_size) {
    const float* feat = (const float*)d_in[0];
    const int*   idxs = (const int*)d_in[1];
    const float* wgt  = (const float*)d_in[2];
    const float* bias = (const float*)d_in[3];
    float* out = (float*)d_out;
    int n = in_sizes[0] / 64;
    int ntiles = (n + 127) / 128;

    wprep_kernel<<<36, 256>>>(wgt);
    scatter_kernel<<<(n + 255) / 256, 256>>>(idxs, n);
    build_kernel<<<(n + 255) / 256, 256>>>(idxs, n);
    center_kernel<<<296, 256>>>(feat, bias, out, n, ntiles);
    tap_kernel<<<296, 256>>>(feat, out);
}

// round 15
// speedup vs baseline: 3.0275x; 1.0161x over previous
#include <cuda_runtime.h>
#include <cuda_fp16.h>
#include <cstdint>

// ---------------------------------------------------------------------------
// Submanifold sparse conv2d, B=4, H=W=1024, C=K=64, 3x3 via fp16
// mma.sync (m16n8k16), single-pass fp16 (err ~3e-4 << 1e-3 gate).
//
//   wprep   : weight -> mma-ready per-lane B fragment records (fp16)
//   scatter : d_grid[flat] = n+1
//   build   : compacted per-tap (out,in) pair lists
//   center  : SMEM-FREE dense tiles: A fragments gathered coalesced from
//             global + cvt in registers; no barriers at all.
//   tap     : persistent pipelined tap tiles (smem staging), red.v4
// Ordering: center's plain stores happen-before tap's reductions via the
// stream -- do NOT fuse (fusion races store vs red, R10).
// ---------------------------------------------------------------------------

typedef unsigned int u32;

#define HH 1024
#define WW 1024
#define NMAX 400000
#define RS  72           // padded A row stride (fp16 elems) = 144 B (tap only)
#define RSB 144

__device__ int  d_grid[1 << 22];          // row+1, 0 = empty (zero-init)
__device__ int2 d_pairs[8][NMAX];
__device__ int  d_cnt[8];
// B fragments: [tap][ks][nc][lane] -> {b0, b1} fp16x2
__device__ uint2 d_wF[9 * 4 * 8 * 32];

#define ATOT (128 * RSB)          // 18432 B: single fp16 A image (tap kernel)

__device__ __forceinline__ u32 smem_u32(const void* p) {
    u32 a; asm("{ .reg .u64 t; cvta.to.shared.u64 t, %1; cvt.u32.u64 %0, t; }" : "=r"(a) : "l"(p));
    return a;
}
// pack two floats to f16x2: low half = first arg, high half = second arg
__device__ __forceinline__ u32 pack_hf(float lo_elem, float hi_elem) {
    u32 r; asm("cvt.rn.f16x2.f32 %0, %1, %2;" : "=r"(r) : "f"(hi_elem), "f"(lo_elem));
    return r;
}
#define LDSM4(r0, r1, r2, r3, addr)                                            \
    asm volatile("ldmatrix.sync.aligned.m8n8.x4.shared.b16 {%0,%1,%2,%3}, [%4];" \
        : "=r"(r0), "=r"(r1), "=r"(r2), "=r"(r3) : "r"(addr))

__device__ __forceinline__ void mma16816(float c[4], const u32 a[4], u32 b0, u32 b1) {
    asm volatile("mma.sync.aligned.m16n8k16.row.col.f32.f16.f16.f32 "
        "{%0,%1,%2,%3}, {%4,%5,%6,%7}, {%8,%9}, {%0,%1,%2,%3};"
        : "+f"(c[0]), "+f"(c[1]), "+f"(c[2]), "+f"(c[3])
        : "r"(a[0]), "r"(a[1]), "r"(a[2]), "r"(a[3]), "r"(b0), "r"(b1));
}

// ---------------- weight prep: mma-ready B fragment records ----------------
// mma.m16n8k16 B fragment: lane l holds b0 = {k0, k0+1}, b1 = {k0+8, k0+9}
// at n = l/4, where k0 = 2*(l%4) within the 16-wide kstep.
__global__ void wprep_kernel(const float* __restrict__ wgt) {
    int idx = blockIdx.x * 256 + threadIdx.x;
    if (idx >= 9 * 4 * 8 * 32) return;
    int lane = idx & 31, nc = (idx >> 5) & 7, ks = (idx >> 8) & 3, tap = idx >> 10;
    int n  = nc * 8 + (lane >> 2);          // kout
    int k0 = ks * 16 + 2 * (lane & 3);      // c (input channel)
    const float* wr = wgt + (n * 9 + tap) * 64;
    uint2 rec;
    rec.x = pack_hf(wr[k0], wr[k0 + 1]);
    rec.y = pack_hf(wr[k0 + 8], wr[k0 + 9]);
    d_wF[idx] = rec;
}

// ---------------- scatter ----------------
__global__ void scatter_kernel(const int* __restrict__ idxs, int n) {
    int gid = blockIdx.x * 256 + threadIdx.x;
    if (gid < 8) d_cnt[gid] = 0;
    if (gid < n) {
        int b = idxs[gid * 3], h = idxs[gid * 3 + 1], w = idxs[gid * 3 + 2];
        d_grid[(b << 20) + (h << 10) + w] = gid + 1;
    }
}

// ---------------- build pair lists ----------------
__global__ void build_kernel(const int* __restrict__ idxs, int n) {
    int gid  = blockIdx.x * 256 + threadIdx.x;
    int warp = threadIdx.x >> 5, lane = threadIdx.x & 31;
    __shared__ int warpoff[8][8];
    __shared__ int blockbase[8];

    bool valid = gid < n;
    int b = 0, h = 0, w = 0;
    if (valid) { b = idxs[gid * 3]; h = idxs[gid * 3 + 1]; w = idxs[gid * 3 + 2]; }

    int nbr[8]; bool act[8]; unsigned masks[8];
#pragma unroll
    for (int tt = 0; tt < 8; tt++) {
        int wt = tt + (tt >= 4 ? 1 : 0);
        int r = wt / 3, s = wt - r * 3;
        int hi = h + r - 1, wi = w + s - 1;
        bool ib = valid && ((unsigned)hi < HH) && ((unsigned)wi < WW);
        int g = 0;
        if (ib) g = d_grid[(b << 20) + (hi << 10) + wi];
        nbr[tt] = g - 1; act[tt] = g > 0;
        masks[tt] = __ballot_sync(0xffffffffu, act[tt]);
    }
    if (lane == 0)
#pragma unroll
        for (int tt = 0; tt < 8; tt++) warpoff[tt][warp] = __popc(masks[tt]);
    __syncthreads();
    if (threadIdx.x < 8) {
        int tt = threadIdx.x, tot = 0;
#pragma unroll
        for (int w2 = 0; w2 < 8; w2++) { int v = warpoff[tt][w2]; warpoff[tt][w2] = tot; tot += v; }
        blockbase[tt] = tot ? atomicAdd(&d_cnt[tt], tot) : 0;
    }
    __syncthreads();
#pragma unroll
    for (int tt = 0; tt < 8; tt++) {
        if (act[tt]) {
            int rank = __popc(masks[tt] & ((1u << lane) - 1u));
            d_pairs[tt][blockbase[tt] + warpoff[tt][warp] + rank] = make_int2(gid, nbr[tt]);
        }
    }
}

// ---------------- tap-kernel helpers (smem path) ----------------
__device__ __forceinline__ void load_rows(const float* __restrict__ feat,
                                          int g, int h, bool valid, float4 fr[8]) {
    if (valid) {
        const float4* p = (const float4*)(feat + (size_t)g * 64) + 8 * h;
#pragma unroll
        for (int j = 0; j < 8; j++) fr[j] = p[j];
    } else {
#pragma unroll
        for (int j = 0; j < 8; j++) fr[j] = make_float4(0.f, 0.f, 0.f, 0.f);
    }
}
__device__ __forceinline__ void stage_from_regs(char* smc, int row, int h, const float4 fr[8]) {
#pragma unroll
    for (int j = 0; j < 4; j++) {
        float4 v0 = fr[2 * j], v1 = fr[2 * j + 1];
        uint4 p;
        p.x = pack_hf(v0.x, v0.y);
        p.y = pack_hf(v0.z, v0.w);
        p.z = pack_hf(v1.x, v1.y);
        p.w = pack_hf(v1.z, v1.w);
        *(uint4*)(smc + row * RSB + h * 64 + j * 16) = p;
    }
}
__device__ __forceinline__ void compute_tile(u32 sb, int lane, int m0, int n0w,
                                             const uint2* __restrict__ wf, float c[2][4][4]) {
    u32 aBase = sb + (u32)(m0 + (lane & 15)) * RSB + (u32)(lane >> 4) * 16;
#pragma unroll
    for (int ks = 0; ks < 4; ks++) {
        u32 ah[2][4];
        LDSM4(ah[0][0], ah[0][1], ah[0][2], ah[0][3], aBase + ks * 32);
        LDSM4(ah[1][0], ah[1][1], ah[1][2], ah[1][3], aBase + ks * 32 + 16 * RSB);
#pragma unroll
        for (int nj = 0; nj < 4; nj++) {
            uint2 f = __ldg(&wf[(ks * 8 + (n0w >> 3) + nj) * 32 + lane]);
#pragma unroll
            for (int mi = 0; mi < 2; mi++)
                mma16816(c[mi][nj], ah[mi], f.x, f.y);
        }
    }
}

// ---------------- center: SMEM-free dense tiles + bias ----------------
// A fragments gathered directly from global (coalesced LDG.64: 8 rows x 32B
// = 8 full sectors per instr), cvt to fp16 in registers. No barriers.
__global__ __launch_bounds__(256, 3) void center_kernel(
        const float* __restrict__ feat, const float* __restrict__ bias,
        float* __restrict__ out, int nn) {
    int t = threadIdx.x, lane = t & 31, wid = t >> 5;
    int gbase = blockIdx.x * 128;
    int m0 = (wid >> 1) * 32, n0w = (wid & 1) * 32;
    int r = lane >> 2, c2 = 2 * (lane & 3);

    const uint2* wf = d_wF + 4 * 1024;     // center tap = 4
    float c[2][4][4];
#pragma unroll
    for (int mi = 0; mi < 2; mi++)
#pragma unroll
        for (int nj = 0; nj < 4; nj++)
#pragma unroll
            for (int e = 0; e < 4; e++) c[mi][nj][e] = 0.f;

#pragma unroll
    for (int ks = 0; ks < 4; ks++) {
        int k0 = ks * 16;
        u32 a[2][4];
#pragma unroll
        for (int mi = 0; mi < 2; mi++) {
            int g0 = gbase + m0 + mi * 16 + r;
            const float* p0 = feat + (size_t)g0 * 64 + k0 + c2;
            const float* p1 = p0 + 8 * 64;
            float2 z = make_float2(0.f, 0.f);
            float2 v0 = (g0     < nn) ? *(const float2*)p0       : z;
            float2 v1 = (g0 + 8 < nn) ? *(const float2*)p1       : z;
            float2 v2 = (g0     < nn) ? *(const float2*)(p0 + 8) : z;
            float2 v3 = (g0 + 8 < nn) ? *(const float2*)(p1 + 8) : z;
            a[mi][0] = pack_hf(v0.x, v0.y);
            a[mi][1] = pack_hf(v1.x, v1.y);
            a[mi][2] = pack_hf(v2.x, v2.y);
            a[mi][3] = pack_hf(v3.x, v3.y);
        }
#pragma unroll
        for (int nj = 0; nj < 4; nj++) {
            uint2 f = __ldg(&wf[(ks * 8 + (n0w >> 3) + nj) * 32 + lane]);
            mma16816(c[0][nj], a[0], f.x, f.y);
            mma16816(c[1][nj], a[1], f.x, f.y);
        }
    }

#pragma unroll
    for (int nj = 0; nj < 4; nj++) {
        int n = n0w + nj * 8 + 2 * (lane & 3);
        float2 bv = __ldg((const float2*)(bias + n));
#pragma unroll
        for (int mi = 0; mi < 2; mi++) {
            int r0 = gbase + m0 + mi * 16 + (lane >> 2);
            int r1 = r0 + 8;
            if (r0 < nn)
                *(float2*)(out + (size_t)r0 * 64 + n) =
                    make_float2(c[mi][nj][0] + bv.x, c[mi][nj][1] + bv.y);
            if (r1 < nn)
                *(float2*)(out + (size_t)r1 * 64 + n) =
                    make_float2(c[mi][nj][2] + bv.x, c[mi][nj][3] + bv.y);
        }
    }
}

// ---------------- taps: persistent pipelined worklist, red.v4 scatter ----------------
__global__ __launch_bounds__(256, 2) void tap_kernel(
        const float* __restrict__ feat, float* __restrict__ out) {
    __shared__ char smc[ATOT];
    __shared__ int2 prs[128];
    u32 sb = smem_u32(smc);
    int t = threadIdx.x, lane = t & 31, wid = t >> 5;
    int row = t >> 1, h = t & 1;
    int m0 = (wid >> 1) * 32, n0w = (wid & 1) * 32;

    // worklist prefix over the 8 tap pair-lists
    int pre[9];
    pre[0] = 0;
#pragma unroll
    for (int tt = 0; tt < 8; tt++) pre[tt + 1] = pre[tt] + ((d_cnt[tt] + 127) >> 7);
    int tot = pre[8];

    int id = blockIdx.x;
    int2 pr = make_int2(-1, 0);
    float4 fr[8];
    if (id < tot) {
        int tap = 0;
#pragma unroll
        for (int tt = 1; tt < 8; tt++) if (id >= pre[tt]) tap = tt;
        int pidx = ((id - pre[tap]) << 7) + row;
        pr = (pidx < d_cnt[tap]) ? d_pairs[tap][pidx] : make_int2(-1, 0);
        load_rows(feat, pr.y, h, true, fr);
    }

    for (; id < tot; id += gridDim.x) {
        __syncthreads();               // previous compute/epilogue done
        if ((t & 1) == 0) prs[row] = pr;
        stage_from_regs(smc, row, h, fr);
        __syncthreads();

        int tap = 0;
#pragma unroll
        for (int tt = 1; tt < 8; tt++) if (id >= pre[tt]) tap = tt;
        int wtap = tap + (tap >= 4 ? 1 : 0);

        // prefetch next tile's pair (feature gather issued after compute)
        int nid = id + gridDim.x;
        int2 prn = make_int2(-1, 0);
        if (nid < tot) {
            int ntap = 0;
#pragma unroll
            for (int tt = 1; tt < 8; tt++) if (nid >= pre[tt]) ntap = tt;
            int pidx = ((nid - pre[ntap]) << 7) + row;
            prn = (pidx < d_cnt[ntap]) ? d_pairs[ntap][pidx] : make_int2(-1, 0);
        }

        float c[2][4][4];
#pragma unroll
        for (int mi = 0; mi < 2; mi++)
#pragma unroll
            for (int nj = 0; nj < 4; nj++)
#pragma unroll
                for (int e = 0; e < 4; e++) c[mi][nj][e] = 0.f;

        compute_tile(sb, lane, m0, n0w, d_wF + wtap * 1024, c);

        // gather next tile's features (latency hidden behind epilogue)
        if (nid < tot) load_rows(feat, prn.y, h, true, fr);
        pr = prn;

        // epilogue: pair lanes (l, l^1) -> 4-wide quads -> red.v4
#pragma unroll
        for (int mi = 0; mi < 2; mi++) {
            int lr = m0 + mi * 16 + (lane >> 2);
            int or0 = prs[lr].x;
            int or1 = prs[lr + 8].x;
#pragma unroll
            for (int nj = 0; nj < 4; nj++) {
                float t0 = __shfl_xor_sync(0xffffffffu, c[mi][nj][0], 1);
                float t1 = __shfl_xor_sync(0xffffffffu, c[mi][nj][1], 1);
                float t2 = __shfl_xor_sync(0xffffffffu, c[mi][nj][2], 1);
                float t3 = __shfl_xor_sync(0xffffffffu, c[mi][nj][3], 1);
                int colb = n0w + nj * 8 + 4 * ((lane & 3) >> 1);
                if ((lane & 1) == 0) {
                    if (or0 >= 0)
                        asm volatile("red.global.add.v4.f32 [%0], {%1, %2, %3, %4};"
                            :: "l"(out + (size_t)or0 * 64 + colb),
                               "f"(c[mi][nj][0]), "f"(c[mi][nj][1]), "f"(t0), "f"(t1) : "memory");
                } else {
                    if (or1 >= 0)
                        asm volatile("red.global.add.v4.f32 [%0], {%1, %2, %3, %4};"
                            :: "l"(out + (size_t)or1 * 64 + colb),
                               "f"(t2), "f"(t3), "f"(c[mi][nj][2]), "f"(c[mi][nj][3]) : "memory");
                }
            }
        }
    }
}

// ---------------- launch ----------------
extern "C" void kernel_launch(void* const* d_in, const int* in_sizes, int n_in,
                              void* d_out, int out_size) {
    const float* feat = (const float*)d_in[0];
    const int*   idxs = (const int*)d_in[1];
    const float* wgt  = (const float*)d_in[2];
    const float* bias = (const float*)d_in[3];
    float* out = (float*)d_out;
    int n = in_sizes[0] / 64;
    int ntiles = (n + 127) / 128;

    wprep_kernel<<<36, 256>>>(wgt);
    scatter_kernel<<<(n + 255) / 256, 256>>>(idxs, n);
    build_kernel<<<(n + 255) / 256, 256>>>(idxs, n);
    center_kernel<<<ntiles, 256>>>(feat, bias, out, n);
    tap_kernel<<<296, 256>>>(feat, out);
}